// round 2
// baseline (speedup 1.0000x reference)
#include <cuda_runtime.h>
#include <math.h>

#define HID     64
#define TWO_H   128
#define TILE    32
#define NTHR    128
#define EPSF    1e-5f
#define SLOPEF  0.2f

#define WS      68          // weight smem row stride (padded)
#define A1S     132         // m buffer row stride (padded)
#define A2S     68          // h buffer row stride (padded)

// shared memory layout (float offsets)
#define OFF_W1  0
#define OFF_W2  (OFF_W1 + 128*WS)
#define OFF_W3  (OFF_W2 + 64*WS)
#define OFF_A1  (OFF_W3 + 64*WS)
#define OFF_A2  (OFF_A1 + TILE*A1S)
#define OFF_G1  (OFF_A2 + TILE*A2S)
#define OFF_B1  (OFF_G1 + 128)
#define OFF_G2  (OFF_B1 + 128)
#define OFF_B2  (OFF_G2 + 64)
#define OFF_G3  (OFF_B2 + 64)
#define OFF_B3  (OFF_G3 + 64)
#define OFF_EW  (OFF_B3 + 64)
#define OFF_TGT (OFF_EW + TILE)
#define SMEM_FLOATS (OFF_TGT + TILE)
#define SMEM_BYTES  (SMEM_FLOATS * 4)

__device__ __forceinline__ void atomic_max_float(float* addr, float v) {
    // order-preserving trick: non-negative floats compare as ints,
    // negative floats compare reversed as unsigned ints.
    if (v >= 0.0f) {
        atomicMax((int*)addr, __float_as_int(v));
    } else {
        atomicMin((unsigned int*)addr, __float_as_uint(v));
    }
}

__global__ void init_kernel(float* __restrict__ out, int n) {
    int i = blockIdx.x * blockDim.x + threadIdx.x;
    if (i < n) out[i] = __int_as_float(0xFF800000);  // -inf
}

__global__ void finalize_kernel(const float* __restrict__ x, float* __restrict__ out, int n) {
    int i = blockIdx.x * blockDim.x + threadIdx.x;
    if (i < n) {
        float v = out[i];
        if (isinf(v)) v = 0.0f;          // isolated nodes -> 0
        out[i] = v + x[i];               // residual
    }
}

__global__ void __launch_bounds__(NTHR, 2)
edge_kernel(const float* __restrict__ x,
            const float* __restrict__ eweight,
            const int* __restrict__ eindex,   // [2, E] int32: row0 src, row1 tgt
            const float* __restrict__ w1,
            const float* __restrict__ w2,
            const float* __restrict__ w3,
            const float* __restrict__ g1, const float* __restrict__ b1,
            const float* __restrict__ g2, const float* __restrict__ b2,
            const float* __restrict__ g3, const float* __restrict__ b3,
            float* __restrict__ out, int E)
{
    extern __shared__ float sm[];
    float* w1s = sm + OFF_W1;
    float* w2s = sm + OFF_W2;
    float* w3s = sm + OFF_W3;
    float* A1  = sm + OFF_A1;
    float* A2  = sm + OFF_A2;
    float* g1s = sm + OFF_G1;
    float* b1s = sm + OFF_B1;
    float* g2s = sm + OFF_G2;
    float* b2s = sm + OFF_B2;
    float* g3s = sm + OFF_G3;
    float* b3s = sm + OFF_B3;
    float* ews = sm + OFF_EW;
    int*   tgts = (int*)(sm + OFF_TGT);

    const int t    = threadIdx.x;
    const int lane = t & 31;
    const int wid  = t >> 5;

    // ---- load weights (transposed) + LN params into smem ----
    for (int idx = t; idx < 64 * 128; idx += NTHR) {
        int c = idx >> 7, k = idx & 127;
        w1s[k * WS + c] = w1[idx];
    }
    for (int idx = t; idx < 64 * 64; idx += NTHR) {
        int c = idx >> 6, k = idx & 63;
        w2s[k * WS + c] = w2[idx];
        w3s[k * WS + c] = w3[idx];
    }
    { g1s[t] = g1[t]; b1s[t] = b1[t]; }
    if (t < 64) { g2s[t] = g2[t]; b2s[t] = b2[t]; g3s[t] = g3[t]; b3s[t] = b3[t]; }

    const int e0 = blockIdx.x * TILE;
    if (t < TILE) {
        int ge = e0 + t;
        if (ge < E) {
            tgts[t] = eindex[E + ge];     // target row (int32)
            ews[t]  = eweight[ge];
        } else {
            tgts[t] = 0;
            ews[t]  = 0.0f;
        }
    }
    __syncthreads();

    // ---- build m = [x_i | w*(x_j - x_i)]  (one row per iteration, coalesced) ----
    #pragma unroll 1
    for (int e = 0; e < TILE; e++) {
        int ge = e0 + e;
        float v = 0.0f;
        if (ge < E) {
            int tg = tgts[e];
            if (t < HID) {
                v = x[(size_t)tg * HID + t];
            } else {
                int f = t - HID;
                int s = eindex[ge];        // source row (int32)
                float xj = x[(size_t)s  * HID + f];
                float xi = x[(size_t)tg * HID + f];
                v = ews[e] * (xj - xi);
            }
        }
        A1[e * A1S + t] = v;
    }
    __syncthreads();

    // ---- LN1 (128) + LeakyReLU, warp per row ----
    for (int e = wid; e < TILE; e += 4) {
        float v0 = A1[e * A1S + lane];
        float v1 = A1[e * A1S + lane + 32];
        float v2 = A1[e * A1S + lane + 64];
        float v3 = A1[e * A1S + lane + 96];
        float s = v0 + v1 + v2 + v3;
        float q = v0 * v0 + v1 * v1 + v2 * v2 + v3 * v3;
        #pragma unroll
        for (int o = 16; o > 0; o >>= 1) {
            s += __shfl_xor_sync(0xffffffffu, s, o);
            q += __shfl_xor_sync(0xffffffffu, q, o);
        }
        float mu   = s * (1.0f / 128.0f);
        float var  = fmaxf(q * (1.0f / 128.0f) - mu * mu, 0.0f);
        float rstd = rsqrtf(var + EPSF);
        float h;
        h = (v0 - mu) * rstd * g1s[lane]      + b1s[lane];      A1[e*A1S+lane]    = h > 0.f ? h : SLOPEF*h;
        h = (v1 - mu) * rstd * g1s[lane + 32] + b1s[lane + 32]; A1[e*A1S+lane+32] = h > 0.f ? h : SLOPEF*h;
        h = (v2 - mu) * rstd * g1s[lane + 64] + b1s[lane + 64]; A1[e*A1S+lane+64] = h > 0.f ? h : SLOPEF*h;
        h = (v3 - mu) * rstd * g1s[lane + 96] + b1s[lane + 96]; A1[e*A1S+lane+96] = h > 0.f ? h : SLOPEF*h;
    }
    __syncthreads();

    const int tr = t >> 4;     // 0..7  -> row group
    const int tc = t & 15;     // 0..15 -> col group
    const int r0 = tr << 2;
    const int c0 = tc << 2;
    float acc[4][4];

    // ---- GEMM1: A2[32x64] = A1[32x128] @ w1s[128x64] ----
    #pragma unroll
    for (int i = 0; i < 4; i++)
        #pragma unroll
        for (int j = 0; j < 4; j++) acc[i][j] = 0.0f;

    #pragma unroll 2
    for (int k = 0; k < TWO_H; k++) {
        float4 bb = *(const float4*)(w1s + k * WS + c0);
        float a0 = A1[(r0 + 0) * A1S + k];
        float a1 = A1[(r0 + 1) * A1S + k];
        float a2 = A1[(r0 + 2) * A1S + k];
        float a3 = A1[(r0 + 3) * A1S + k];
        acc[0][0] += a0*bb.x; acc[0][1] += a0*bb.y; acc[0][2] += a0*bb.z; acc[0][3] += a0*bb.w;
        acc[1][0] += a1*bb.x; acc[1][1] += a1*bb.y; acc[1][2] += a1*bb.z; acc[1][3] += a1*bb.w;
        acc[2][0] += a2*bb.x; acc[2][1] += a2*bb.y; acc[2][2] += a2*bb.z; acc[2][3] += a2*bb.w;
        acc[3][0] += a3*bb.x; acc[3][1] += a3*bb.y; acc[3][2] += a3*bb.z; acc[3][3] += a3*bb.w;
    }
    #pragma unroll
    for (int i = 0; i < 4; i++)
        *(float4*)(A2 + (r0 + i) * A2S + c0) = make_float4(acc[i][0], acc[i][1], acc[i][2], acc[i][3]);
    __syncthreads();

    // ---- LN2 (64) + act ----
    for (int e = wid; e < TILE; e += 4) {
        float v0 = A2[e * A2S + lane];
        float v1 = A2[e * A2S + lane + 32];
        float s = v0 + v1;
        float q = v0 * v0 + v1 * v1;
        #pragma unroll
        for (int o = 16; o > 0; o >>= 1) {
            s += __shfl_xor_sync(0xffffffffu, s, o);
            q += __shfl_xor_sync(0xffffffffu, q, o);
        }
        float mu   = s * (1.0f / 64.0f);
        float var  = fmaxf(q * (1.0f / 64.0f) - mu * mu, 0.0f);
        float rstd = rsqrtf(var + EPSF);
        float h;
        h = (v0 - mu) * rstd * g2s[lane]      + b2s[lane];      A2[e*A2S+lane]    = h > 0.f ? h : SLOPEF*h;
        h = (v1 - mu) * rstd * g2s[lane + 32] + b2s[lane + 32]; A2[e*A2S+lane+32] = h > 0.f ? h : SLOPEF*h;
    }
    __syncthreads();

    // ---- GEMM2: B2[32x64] = A2 @ w2s  (B2 reuses A1 storage, stride A2S) ----
    float* B2 = A1;
    #pragma unroll
    for (int i = 0; i < 4; i++)
        #pragma unroll
        for (int j = 0; j < 4; j++) acc[i][j] = 0.0f;

    #pragma unroll 2
    for (int k = 0; k < HID; k++) {
        float4 bb = *(const float4*)(w2s + k * WS + c0);
        float a0 = A2[(r0 + 0) * A2S + k];
        float a1 = A2[(r0 + 1) * A2S + k];
        float a2 = A2[(r0 + 2) * A2S + k];
        float a3 = A2[(r0 + 3) * A2S + k];
        acc[0][0] += a0*bb.x; acc[0][1] += a0*bb.y; acc[0][2] += a0*bb.z; acc[0][3] += a0*bb.w;
        acc[1][0] += a1*bb.x; acc[1][1] += a1*bb.y; acc[1][2] += a1*bb.z; acc[1][3] += a1*bb.w;
        acc[2][0] += a2*bb.x; acc[2][1] += a2*bb.y; acc[2][2] += a2*bb.z; acc[2][3] += a2*bb.w;
        acc[3][0] += a3*bb.x; acc[3][1] += a3*bb.y; acc[3][2] += a3*bb.z; acc[3][3] += a3*bb.w;
    }
    __syncthreads();   // everyone done reading A2 and old A1 before overwrite
    #pragma unroll
    for (int i = 0; i < 4; i++)
        *(float4*)(B2 + (r0 + i) * A2S + c0) = make_float4(acc[i][0], acc[i][1], acc[i][2], acc[i][3]);
    __syncthreads();

    // ---- LN3 (64) + act on B2 ----
    for (int e = wid; e < TILE; e += 4) {
        float v0 = B2[e * A2S + lane];
        float v1 = B2[e * A2S + lane + 32];
        float s = v0 + v1;
        float q = v0 * v0 + v1 * v1;
        #pragma unroll
        for (int o = 16; o > 0; o >>= 1) {
            s += __shfl_xor_sync(0xffffffffu, s, o);
            q += __shfl_xor_sync(0xffffffffu, q, o);
        }
        float mu   = s * (1.0f / 64.0f);
        float var  = fmaxf(q * (1.0f / 64.0f) - mu * mu, 0.0f);
        float rstd = rsqrtf(var + EPSF);
        float h;
        h = (v0 - mu) * rstd * g3s[lane]      + b3s[lane];      B2[e*A2S+lane]    = h > 0.f ? h : SLOPEF*h;
        h = (v1 - mu) * rstd * g3s[lane + 32] + b3s[lane + 32]; B2[e*A2S+lane+32] = h > 0.f ? h : SLOPEF*h;
    }
    __syncthreads();

    // ---- GEMM3: msg[32x64] = B2 @ w3s, fused segment-max epilogue ----
    #pragma unroll
    for (int i = 0; i < 4; i++)
        #pragma unroll
        for (int j = 0; j < 4; j++) acc[i][j] = 0.0f;

    #pragma unroll 2
    for (int k = 0; k < HID; k++) {
        float4 bb = *(const float4*)(w3s + k * WS + c0);
        float a0 = B2[(r0 + 0) * A2S + k];
        float a1 = B2[(r0 + 1) * A2S + k];
        float a2 = B2[(r0 + 2) * A2S + k];
        float a3 = B2[(r0 + 3) * A2S + k];
        acc[0][0] += a0*bb.x; acc[0][1] += a0*bb.y; acc[0][2] += a0*bb.z; acc[0][3] += a0*bb.w;
        acc[1][0] += a1*bb.x; acc[1][1] += a1*bb.y; acc[1][2] += a1*bb.z; acc[1][3] += a1*bb.w;
        acc[2][0] += a2*bb.x; acc[2][1] += a2*bb.y; acc[2][2] += a2*bb.z; acc[2][3] += a2*bb.w;
        acc[3][0] += a3*bb.x; acc[3][1] += a3*bb.y; acc[3][2] += a3*bb.z; acc[3][3] += a3*bb.w;
    }

    #pragma unroll
    for (int i = 0; i < 4; i++) {
        int e  = r0 + i;
        int ge = e0 + e;
        if (ge < E) {
            float* base = out + (size_t)tgts[e] * HID + c0;
            #pragma unroll
            for (int j = 0; j < 4; j++) atomic_max_float(base + j, acc[i][j]);
        }
    }
}

extern "C" void kernel_launch(void* const* d_in, const int* in_sizes, int n_in,
                              void* d_out, int out_size) {
    const float* x  = (const float*)d_in[0];
    const float* ew = (const float*)d_in[1];
    const int*   ei = (const int*)d_in[2];    // int32: JAX x64 disabled downcasts int64
    const float* w1 = (const float*)d_in[3];
    const float* w2 = (const float*)d_in[4];
    const float* w3 = (const float*)d_in[5];
    const float* g1 = (const float*)d_in[6];
    const float* b1 = (const float*)d_in[7];
    const float* g2 = (const float*)d_in[8];
    const float* b2 = (const float*)d_in[9];
    const float* g3 = (const float*)d_in[10];
    const float* b3 = (const float*)d_in[11];
    float* out = (float*)d_out;

    const int E  = in_sizes[1];   // edge_weight element count
    const int NH = out_size;      // N * H

    cudaFuncSetAttribute(edge_kernel, cudaFuncAttributeMaxDynamicSharedMemorySize, SMEM_BYTES);

    init_kernel<<<(NH + 255) / 256, 256>>>(out, NH);
    edge_kernel<<<(E + TILE - 1) / TILE, NTHR, SMEM_BYTES>>>(
        x, ew, ei, w1, w2, w3, g1, b1, g2, b2, g3, b3, out, E);
    finalize_kernel<<<(NH + 255) / 256, 256>>>(x, out, NH);
}

// round 3
// speedup vs baseline: 1.4826x; 1.4826x over previous
#include <cuda_runtime.h>
#include <math.h>

#define HID     64
#define TWO_H   128
#define TILE    128
#define NTHR    256
#define EPSF    1e-5f
#define SLOPEF  0.2f

#define WS      64           // weight smem row stride (B rows read whole, no pad needed)
#define A1S     132          // m buffer row stride (132 mod 8 = 4 -> adjacent rows 4 banks apart)
#define A2S     68           // h buffer row stride (68 mod 8 = 4)

// shared memory layout (float offsets)
#define OFF_W1  0
#define OFF_W2  (OFF_W1 + 128*WS)
#define OFF_W3  (OFF_W2 + 64*WS)
#define OFF_A1  (OFF_W3 + 64*WS)
#define OFF_A2  (OFF_A1 + TILE*A1S)
#define OFF_G1  (OFF_A2 + TILE*A2S)
#define OFF_B1  (OFF_G1 + 128)
#define OFF_G2  (OFF_B1 + 128)
#define OFF_B2  (OFF_G2 + 64)
#define OFF_G3  (OFF_B2 + 64)
#define OFF_B3  (OFF_G3 + 64)
#define OFF_EW  (OFF_B3 + 64)
#define OFF_TGT (OFF_EW + TILE)
#define SMEM_FLOATS (OFF_TGT + TILE)
#define SMEM_BYTES  (SMEM_FLOATS * 4)

__device__ __forceinline__ void atomic_max_float(float* addr, float v) {
    if (v >= 0.0f) {
        atomicMax((int*)addr, __float_as_int(v));
    } else {
        atomicMin((unsigned int*)addr, __float_as_uint(v));
    }
}

__global__ void init_kernel(float* __restrict__ out, int n) {
    int i = blockIdx.x * blockDim.x + threadIdx.x;
    if (i < n) out[i] = __int_as_float(0xFF800000);  // -inf
}

__global__ void finalize_kernel(const float* __restrict__ x, float* __restrict__ out, int n) {
    int i = blockIdx.x * blockDim.x + threadIdx.x;
    if (i < n) {
        float v = out[i];
        if (isinf(v)) v = 0.0f;
        out[i] = v + x[i];
    }
}

__global__ void __launch_bounds__(NTHR, 1)
edge_kernel(const float* __restrict__ x,
            const float* __restrict__ eweight,
            const int* __restrict__ eindex,   // [2, E] int32: row0 src, row1 tgt
            const float* __restrict__ w1,
            const float* __restrict__ w2,
            const float* __restrict__ w3,
            const float* __restrict__ g1, const float* __restrict__ b1,
            const float* __restrict__ g2, const float* __restrict__ b2,
            const float* __restrict__ g3, const float* __restrict__ b3,
            float* __restrict__ out, int E)
{
    extern __shared__ float sm[];
    float* w1s = sm + OFF_W1;
    float* w2s = sm + OFF_W2;
    float* w3s = sm + OFF_W3;
    float* A1  = sm + OFF_A1;
    float* A2  = sm + OFF_A2;
    float* g1s = sm + OFF_G1;
    float* b1s = sm + OFF_B1;
    float* g2s = sm + OFF_G2;
    float* b2s = sm + OFF_B2;
    float* g3s = sm + OFF_G3;
    float* b3s = sm + OFF_B3;
    float* ews = sm + OFF_EW;
    int*   tgts = (int*)(sm + OFF_TGT);

    const int t    = threadIdx.x;
    const int lane = t & 31;
    const int wid  = t >> 5;
    const int e0   = blockIdx.x * TILE;

    // ---- stage weights (transposed), LN params, edge meta ----
    for (int idx = t; idx < 64 * 128; idx += NTHR) {
        int c = idx >> 7, k = idx & 127;
        w1s[k * WS + c] = w1[idx];
    }
    for (int idx = t; idx < 64 * 64; idx += NTHR) {
        int c = idx >> 6, k = idx & 63;
        w2s[k * WS + c] = w2[idx];
        w3s[k * WS + c] = w3[idx];
    }
    if (t < 128) { g1s[t] = g1[t]; b1s[t] = b1[t]; }
    else {
        int u = t - 128;
        if (u < 64) { g2s[u] = g2[u]; b2s[u] = b2[u]; g3s[u] = g3[u]; b3s[u] = b3[u]; }
    }
    if (t < TILE) {
        int ge = e0 + t;
        if (ge < E) {
            tgts[t] = eindex[E + ge];
            ews[t]  = eweight[ge];
        } else {
            tgts[t] = 0;
            ews[t]  = 0.0f;
        }
    }
    __syncthreads();

    // ---- build m = [x_i | w*(x_j - x_i)], one thread per (edge, half) ----
    {
        const int r  = t >> 1;       // edge row 0..127
        const int h  = t & 1;        // 0: x_i half, 1: weighted-diff half
        const int ge = e0 + r;
        float4* dst = (float4*)(A1 + r * A1S + h * 64);
        if (ge < E) {
            int tg = tgts[r];
            const float4* xi = (const float4*)(x + (size_t)tg * HID);
            if (h == 0) {
                #pragma unroll
                for (int f = 0; f < 16; f++) dst[f] = xi[f];
            } else {
                int s = eindex[ge];
                float w = ews[r];
                const float4* xj = (const float4*)(x + (size_t)s * HID);
                #pragma unroll
                for (int f = 0; f < 16; f++) {
                    float4 a = xj[f], b = xi[f];
                    dst[f] = make_float4(w*(a.x-b.x), w*(a.y-b.y), w*(a.z-b.z), w*(a.w-b.w));
                }
            }
        } else {
            #pragma unroll
            for (int f = 0; f < 16; f++) dst[f] = make_float4(0.f,0.f,0.f,0.f);
        }
    }
    __syncthreads();

    // ---- LN1 (width 128) + LeakyReLU, warp per row ----
    #pragma unroll 2
    for (int e = wid; e < TILE; e += 8) {
        float* row = A1 + e * A1S;
        float v0 = row[lane];
        float v1 = row[lane + 32];
        float v2 = row[lane + 64];
        float v3 = row[lane + 96];
        float s = v0 + v1 + v2 + v3;
        float q = v0*v0 + v1*v1 + v2*v2 + v3*v3;
        #pragma unroll
        for (int o = 16; o > 0; o >>= 1) {
            s += __shfl_xor_sync(0xffffffffu, s, o);
            q += __shfl_xor_sync(0xffffffffu, q, o);
        }
        float mu   = s * (1.0f / 128.0f);
        float var  = fmaxf(q * (1.0f / 128.0f) - mu * mu, 0.0f);
        float rstd = rsqrtf(var + EPSF);
        float h;
        h = (v0 - mu) * rstd * g1s[lane]      + b1s[lane];      row[lane]    = h > 0.f ? h : SLOPEF*h;
        h = (v1 - mu) * rstd * g1s[lane + 32] + b1s[lane + 32]; row[lane+32] = h > 0.f ? h : SLOPEF*h;
        h = (v2 - mu) * rstd * g1s[lane + 64] + b1s[lane + 64]; row[lane+64] = h > 0.f ? h : SLOPEF*h;
        h = (v3 - mu) * rstd * g1s[lane + 96] + b1s[lane + 96]; row[lane+96] = h > 0.f ? h : SLOPEF*h;
    }
    __syncthreads();

    // thread tile: rows rg+32i (i=0..3), cols {4cg..4cg+3} U {4cg+32..4cg+35}
    const int cg = t & 7;
    const int rg = t >> 3;          // 0..31
    const int cA = 4 * cg;          // first col group
    float acc[4][8];

    // ---- GEMM1: A2[128x64] = A1[128x128] @ w1s ----
    #pragma unroll
    for (int i = 0; i < 4; i++)
        #pragma unroll
        for (int j = 0; j < 8; j++) acc[i][j] = 0.0f;

    #pragma unroll 4
    for (int k = 0; k < TWO_H; k++) {
        float4 b0 = *(const float4*)(w1s + k * WS + cA);
        float4 b1 = *(const float4*)(w1s + k * WS + cA + 32);
        #pragma unroll
        for (int i = 0; i < 4; i++) {
            float a = A1[(rg + 32*i) * A1S + k];
            acc[i][0] += a*b0.x; acc[i][1] += a*b0.y; acc[i][2] += a*b0.z; acc[i][3] += a*b0.w;
            acc[i][4] += a*b1.x; acc[i][5] += a*b1.y; acc[i][6] += a*b1.z; acc[i][7] += a*b1.w;
        }
    }
    #pragma unroll
    for (int i = 0; i < 4; i++) {
        float* o = A2 + (rg + 32*i) * A2S;
        *(float4*)(o + cA)      = make_float4(acc[i][0], acc[i][1], acc[i][2], acc[i][3]);
        *(float4*)(o + cA + 32) = make_float4(acc[i][4], acc[i][5], acc[i][6], acc[i][7]);
    }
    __syncthreads();

    // ---- LN2 (width 64) + act ----
    #pragma unroll 2
    for (int e = wid; e < TILE; e += 8) {
        float* row = A2 + e * A2S;
        float v0 = row[lane];
        float v1 = row[lane + 32];
        float s = v0 + v1;
        float q = v0*v0 + v1*v1;
        #pragma unroll
        for (int o = 16; o > 0; o >>= 1) {
            s += __shfl_xor_sync(0xffffffffu, s, o);
            q += __shfl_xor_sync(0xffffffffu, q, o);
        }
        float mu   = s * (1.0f / 64.0f);
        float var  = fmaxf(q * (1.0f / 64.0f) - mu * mu, 0.0f);
        float rstd = rsqrtf(var + EPSF);
        float h;
        h = (v0 - mu) * rstd * g2s[lane]      + b2s[lane];      row[lane]    = h > 0.f ? h : SLOPEF*h;
        h = (v1 - mu) * rstd * g2s[lane + 32] + b2s[lane + 32]; row[lane+32] = h > 0.f ? h : SLOPEF*h;
    }
    __syncthreads();

    // ---- GEMM2: B2[128x64] = A2 @ w2s (B2 reuses A1 storage, stride A2S) ----
    float* B2 = A1;
    #pragma unroll
    for (int i = 0; i < 4; i++)
        #pragma unroll
        for (int j = 0; j < 8; j++) acc[i][j] = 0.0f;

    #pragma unroll 4
    for (int k = 0; k < HID; k++) {
        float4 b0 = *(const float4*)(w2s + k * WS + cA);
        float4 b1 = *(const float4*)(w2s + k * WS + cA + 32);
        #pragma unroll
        for (int i = 0; i < 4; i++) {
            float a = A2[(rg + 32*i) * A2S + k];
            acc[i][0] += a*b0.x; acc[i][1] += a*b0.y; acc[i][2] += a*b0.z; acc[i][3] += a*b0.w;
            acc[i][4] += a*b1.x; acc[i][5] += a*b1.y; acc[i][6] += a*b1.z; acc[i][7] += a*b1.w;
        }
    }
    // A1 region is dead (GEMM2 reads only A2) -> safe to write without a barrier
    #pragma unroll
    for (int i = 0; i < 4; i++) {
        float* o = B2 + (rg + 32*i) * A2S;
        *(float4*)(o + cA)      = make_float4(acc[i][0], acc[i][1], acc[i][2], acc[i][3]);
        *(float4*)(o + cA + 32) = make_float4(acc[i][4], acc[i][5], acc[i][6], acc[i][7]);
    }
    __syncthreads();

    // ---- LN3 (width 64) + act on B2 ----
    #pragma unroll 2
    for (int e = wid; e < TILE; e += 8) {
        float* row = B2 + e * A2S;
        float v0 = row[lane];
        float v1 = row[lane + 32];
        float s = v0 + v1;
        float q = v0*v0 + v1*v1;
        #pragma unroll
        for (int o = 16; o > 0; o >>= 1) {
            s += __shfl_xor_sync(0xffffffffu, s, o);
            q += __shfl_xor_sync(0xffffffffu, q, o);
        }
        float mu   = s * (1.0f / 64.0f);
        float var  = fmaxf(q * (1.0f / 64.0f) - mu * mu, 0.0f);
        float rstd = rsqrtf(var + EPSF);
        float h;
        h = (v0 - mu) * rstd * g3s[lane]      + b3s[lane];      row[lane]    = h > 0.f ? h : SLOPEF*h;
        h = (v1 - mu) * rstd * g3s[lane + 32] + b3s[lane + 32]; row[lane+32] = h > 0.f ? h : SLOPEF*h;
    }
    __syncthreads();

    // ---- GEMM3: msg = B2 @ w3s, fused segment-max epilogue ----
    #pragma unroll
    for (int i = 0; i < 4; i++)
        #pragma unroll
        for (int j = 0; j < 8; j++) acc[i][j] = 0.0f;

    #pragma unroll 4
    for (int k = 0; k < HID; k++) {
        float4 b0 = *(const float4*)(w3s + k * WS + cA);
        float4 b1 = *(const float4*)(w3s + k * WS + cA + 32);
        #pragma unroll
        for (int i = 0; i < 4; i++) {
            float a = B2[(rg + 32*i) * A2S + k];
            acc[i][0] += a*b0.x; acc[i][1] += a*b0.y; acc[i][2] += a*b0.z; acc[i][3] += a*b0.w;
            acc[i][4] += a*b1.x; acc[i][5] += a*b1.y; acc[i][6] += a*b1.z; acc[i][7] += a*b1.w;
        }
    }

    #pragma unroll
    for (int i = 0; i < 4; i++) {
        int e  = rg + 32*i;
        int ge = e0 + e;
        if (ge < E) {
            float* base = out + (size_t)tgts[e] * HID + cA;
            #pragma unroll
            for (int j = 0; j < 4; j++) atomic_max_float(base + j, acc[i][j]);
            #pragma unroll
            for (int j = 0; j < 4; j++) atomic_max_float(base + 32 + j, acc[i][4 + j]);
        }
    }
}

extern "C" void kernel_launch(void* const* d_in, const int* in_sizes, int n_in,
                              void* d_out, int out_size) {
    const float* x  = (const float*)d_in[0];
    const float* ew = (const float*)d_in[1];
    const int*   ei = (const int*)d_in[2];
    const float* w1 = (const float*)d_in[3];
    const float* w2 = (const float*)d_in[4];
    const float* w3 = (const float*)d_in[5];
    const float* g1 = (const float*)d_in[6];
    const float* b1 = (const float*)d_in[7];
    const float* g2 = (const float*)d_in[8];
    const float* b2 = (const float*)d_in[9];
    const float* g3 = (const float*)d_in[10];
    const float* b3 = (const float*)d_in[11];
    float* out = (float*)d_out;

    const int E  = in_sizes[1];
    const int NH = out_size;

    cudaFuncSetAttribute(edge_kernel, cudaFuncAttributeMaxDynamicSharedMemorySize, SMEM_BYTES);

    init_kernel<<<(NH + 255) / 256, 256>>>(out, NH);
    edge_kernel<<<(E + TILE - 1) / TILE, NTHR, SMEM_BYTES>>>(
        x, ew, ei, w1, w2, w3, g1, b1, g2, b2, g3, b3, out, E);
    finalize_kernel<<<(NH + 255) / 256, 256>>>(x, out, NH);
}

// round 4
// speedup vs baseline: 2.5459x; 1.7172x over previous
#include <cuda_runtime.h>
#include <math.h>
#include <stdint.h>

#define HID     64
#define TWO_H   128
#define TILE    128
#define NTHR    256
#define EPSF    1e-5f
#define SLOPEF  0.2f

#define WS      72           // weight smem row stride: B-frag banks (8q+grp)%32 conflict-free
#define A1S     132          // m buffer row stride: A-frag banks (4grp+q)%32 conflict-free
#define A2S     68           // h buffer row stride

// shared memory layout (float offsets)
#define OFF_W1  0
#define OFF_W2  (OFF_W1 + 128*WS)
#define OFF_W3  (OFF_W2 + 64*WS)
#define OFF_A1  (OFF_W3 + 64*WS)
#define OFF_A2  (OFF_A1 + TILE*A1S)
#define OFF_G1  (OFF_A2 + TILE*A2S)
#define OFF_B1  (OFF_G1 + 128)
#define OFF_G2  (OFF_B1 + 128)
#define OFF_B2  (OFF_G2 + 64)
#define OFF_G3  (OFF_B2 + 64)
#define OFF_B3  (OFF_G3 + 64)
#define OFF_EW  (OFF_B3 + 64)
#define OFF_TGT (OFF_EW + TILE)
#define SMEM_FLOATS (OFF_TGT + TILE)
#define SMEM_BYTES  (SMEM_FLOATS * 4)

// monotone float->uint transform: a >= b  <=>  key(a) >= key(b) (unsigned)
__device__ __forceinline__ unsigned fkey(float v) {
    unsigned u = __float_as_uint(v);
    return u ^ (unsigned)(((int)u >> 31) | 0x80000000);
}
// key(-inf) = ~0xFF800000 = 0x007FFFFF
#define KEY_NEG_INF 0x007FFFFFu

__device__ __forceinline__ uint32_t f2tf32(float f) {
    uint32_t r;
    asm("cvt.rna.tf32.f32 %0, %1;" : "=r"(r) : "f"(f));
    return r;
}

__device__ __forceinline__ void mma_tf32(float acc[4],
                                         uint32_t a0, uint32_t a1, uint32_t a2, uint32_t a3,
                                         uint32_t b0, uint32_t b1) {
    asm volatile(
        "mma.sync.aligned.m16n8k8.row.col.f32.tf32.tf32.f32 "
        "{%0,%1,%2,%3}, {%4,%5,%6,%7}, {%8,%9}, {%0,%1,%2,%3};"
        : "+f"(acc[0]), "+f"(acc[1]), "+f"(acc[2]), "+f"(acc[3])
        : "r"(a0), "r"(a1), "r"(a2), "r"(a3), "r"(b0), "r"(b1));
}

__global__ void init_kernel(unsigned* __restrict__ out, int n) {
    int i = blockIdx.x * blockDim.x + threadIdx.x;
    if (i < n) out[i] = KEY_NEG_INF;
}

__global__ void finalize_kernel(const float* __restrict__ x, float* __restrict__ out, int n) {
    int i = blockIdx.x * blockDim.x + threadIdx.x;
    if (i < n) {
        unsigned u = ((const unsigned*)out)[i];
        unsigned bits = (u & 0x80000000u) ? (u ^ 0x80000000u) : ~u;
        float v = __uint_as_float(bits);
        if (isinf(v)) v = 0.0f;          // untouched (-inf) -> 0
        out[i] = v + x[i];               // residual
    }
}

__global__ void __launch_bounds__(NTHR, 1)
edge_kernel(const float* __restrict__ x,
            const float* __restrict__ eweight,
            const int* __restrict__ eindex,   // [2, E] int32: row0 src, row1 tgt
            const float* __restrict__ w1,
            const float* __restrict__ w2,
            const float* __restrict__ w3,
            const float* __restrict__ g1, const float* __restrict__ b1,
            const float* __restrict__ g2, const float* __restrict__ b2,
            const float* __restrict__ g3, const float* __restrict__ b3,
            float* __restrict__ out, int E)
{
    extern __shared__ float sm[];
    float*    A1  = sm + OFF_A1;
    float*    A2  = sm + OFF_A2;
    uint32_t* w1u = (uint32_t*)(sm + OFF_W1);
    uint32_t* w2u = (uint32_t*)(sm + OFF_W2);
    uint32_t* w3u = (uint32_t*)(sm + OFF_W3);
    float* g1s = sm + OFF_G1;
    float* b1s = sm + OFF_B1;
    float* g2s = sm + OFF_G2;
    float* b2s = sm + OFF_B2;
    float* g3s = sm + OFF_G3;
    float* b3s = sm + OFF_B3;
    float* ews = sm + OFF_EW;
    int*   tgts = (int*)(sm + OFF_TGT);

    const int t    = threadIdx.x;
    const int lane = t & 31;
    const int wid  = t >> 5;
    const int e0   = blockIdx.x * TILE;

    // ---- stage weights transposed + tf32-rounded (float4 gather, conflict-free STS) ----
    for (int i = t; i < 2048; i += NTHR) {          // w1: 64c x 128k
        int c = i & 63, k = (i >> 6) << 2;
        float4 v = *(const float4*)(w1 + c * TWO_H + k);
        w1u[(k + 0) * WS + c] = f2tf32(v.x);
        w1u[(k + 1) * WS + c] = f2tf32(v.y);
        w1u[(k + 2) * WS + c] = f2tf32(v.z);
        w1u[(k + 3) * WS + c] = f2tf32(v.w);
    }
    for (int i = t; i < 1024; i += NTHR) {          // w2, w3: 64c x 64k
        int c = i & 63, k = (i >> 6) << 2;
        float4 v2 = *(const float4*)(w2 + c * HID + k);
        float4 v3 = *(const float4*)(w3 + c * HID + k);
        w2u[(k + 0) * WS + c] = f2tf32(v2.x);
        w2u[(k + 1) * WS + c] = f2tf32(v2.y);
        w2u[(k + 2) * WS + c] = f2tf32(v2.z);
        w2u[(k + 3) * WS + c] = f2tf32(v2.w);
        w3u[(k + 0) * WS + c] = f2tf32(v3.x);
        w3u[(k + 1) * WS + c] = f2tf32(v3.y);
        w3u[(k + 2) * WS + c] = f2tf32(v3.z);
        w3u[(k + 3) * WS + c] = f2tf32(v3.w);
    }
    if (t < 128) { g1s[t] = g1[t]; b1s[t] = b1[t]; }
    else {
        int u = t - 128;
        if (u < 64) { g2s[u] = g2[u]; b2s[u] = b2[u]; g3s[u] = g3[u]; b3s[u] = b3[u]; }
    }
    if (t < TILE) {
        int ge = e0 + t;
        if (ge < E) {
            tgts[t] = eindex[E + ge];
            ews[t]  = eweight[ge];
        } else {
            tgts[t] = 0;
            ews[t]  = 0.0f;
        }
    }
    __syncthreads();

    // ---- build m = [x_i | w*(x_j - x_i)], one thread per (edge, half) ----
    {
        const int r  = t >> 1;
        const int h  = t & 1;
        const int ge = e0 + r;
        float4* dst = (float4*)(A1 + r * A1S + h * 64);
        if (ge < E) {
            int tg = tgts[r];
            const float4* xi = (const float4*)(x + (size_t)tg * HID);
            if (h == 0) {
                #pragma unroll
                for (int f = 0; f < 16; f++) dst[f] = xi[f];
            } else {
                int s = eindex[ge];
                float w = ews[r];
                const float4* xj = (const float4*)(x + (size_t)s * HID);
                #pragma unroll
                for (int f = 0; f < 16; f++) {
                    float4 a = xj[f], b = xi[f];
                    dst[f] = make_float4(w*(a.x-b.x), w*(a.y-b.y), w*(a.z-b.z), w*(a.w-b.w));
                }
            }
        } else {
            #pragma unroll
            for (int f = 0; f < 16; f++) dst[f] = make_float4(0.f,0.f,0.f,0.f);
        }
    }
    __syncthreads();

    // ---- LN1 (width 128) + LeakyReLU, tf32-rounded writeback ----
    #pragma unroll 2
    for (int e = wid; e < TILE; e += 8) {
        float* row = A1 + e * A1S;
        float v0 = row[lane];
        float v1 = row[lane + 32];
        float v2 = row[lane + 64];
        float v3 = row[lane + 96];
        float s = v0 + v1 + v2 + v3;
        float q = v0*v0 + v1*v1 + v2*v2 + v3*v3;
        #pragma unroll
        for (int o = 16; o > 0; o >>= 1) {
            s += __shfl_xor_sync(0xffffffffu, s, o);
            q += __shfl_xor_sync(0xffffffffu, q, o);
        }
        float mu   = s * (1.0f / 128.0f);
        float var  = fmaxf(q * (1.0f / 128.0f) - mu * mu, 0.0f);
        float rstd = rsqrtf(var + EPSF);
        float h;
        h = (v0 - mu) * rstd * g1s[lane]      + b1s[lane];      row[lane]    = __uint_as_float(f2tf32(h > 0.f ? h : SLOPEF*h));
        h = (v1 - mu) * rstd * g1s[lane + 32] + b1s[lane + 32]; row[lane+32] = __uint_as_float(f2tf32(h > 0.f ? h : SLOPEF*h));
        h = (v2 - mu) * rstd * g1s[lane + 64] + b1s[lane + 64]; row[lane+64] = __uint_as_float(f2tf32(h > 0.f ? h : SLOPEF*h));
        h = (v3 - mu) * rstd * g1s[lane + 96] + b1s[lane + 96]; row[lane+96] = __uint_as_float(f2tf32(h > 0.f ? h : SLOPEF*h));
    }
    __syncthreads();

    const int grp = lane >> 2;   // 0..7
    const int q   = lane & 3;    // 0..3
    const int r0  = wid * 16;    // warp's 16-row tile
    float acc[8][4];

    // ---- GEMM1: A2[128x64] = A1[128x128] @ W1^T (tf32 HMMA) ----
    #pragma unroll
    for (int nt = 0; nt < 8; nt++)
        #pragma unroll
        for (int j = 0; j < 4; j++) acc[nt][j] = 0.0f;

    {
        const uint32_t* Abase = (const uint32_t*)A1 + (r0 + grp) * A1S + q;
        #pragma unroll
        for (int kt = 0; kt < 16; kt++) {
            const int k0 = kt * 8;
            uint32_t a0 = Abase[k0];
            uint32_t a1 = Abase[8 * A1S + k0];
            uint32_t a2 = Abase[k0 + 4];
            uint32_t a3 = Abase[8 * A1S + k0 + 4];
            #pragma unroll
            for (int nt = 0; nt < 8; nt++) {
                uint32_t b0 = w1u[(k0 + q) * WS + nt * 8 + grp];
                uint32_t b1 = w1u[(k0 + 4 + q) * WS + nt * 8 + grp];
                mma_tf32(acc[nt], a0, a1, a2, a3, b0, b1);
            }
        }
    }
    #pragma unroll
    for (int nt = 0; nt < 8; nt++) {
        float* o = A2 + (r0 + grp) * A2S + nt * 8 + 2 * q;
        *(float2*)o             = make_float2(acc[nt][0], acc[nt][1]);
        *(float2*)(o + 8 * A2S) = make_float2(acc[nt][2], acc[nt][3]);
    }
    __syncthreads();

    // ---- LN2 (width 64) + act, tf32 writeback ----
    #pragma unroll 2
    for (int e = wid; e < TILE; e += 8) {
        float* row = A2 + e * A2S;
        float v0 = row[lane];
        float v1 = row[lane + 32];
        float s = v0 + v1;
        float qq = v0*v0 + v1*v1;
        #pragma unroll
        for (int o = 16; o > 0; o >>= 1) {
            s  += __shfl_xor_sync(0xffffffffu, s, o);
            qq += __shfl_xor_sync(0xffffffffu, qq, o);
        }
        float mu   = s * (1.0f / 64.0f);
        float var  = fmaxf(qq * (1.0f / 64.0f) - mu * mu, 0.0f);
        float rstd = rsqrtf(var + EPSF);
        float h;
        h = (v0 - mu) * rstd * g2s[lane]      + b2s[lane];      row[lane]    = __uint_as_float(f2tf32(h > 0.f ? h : SLOPEF*h));
        h = (v1 - mu) * rstd * g2s[lane + 32] + b2s[lane + 32]; row[lane+32] = __uint_as_float(f2tf32(h > 0.f ? h : SLOPEF*h));
    }
    __syncthreads();

    // ---- GEMM2: B2[128x64] = A2 @ W2^T (B2 reuses A1 storage, stride A2S) ----
    float* B2 = A1;
    #pragma unroll
    for (int nt = 0; nt < 8; nt++)
        #pragma unroll
        for (int j = 0; j < 4; j++) acc[nt][j] = 0.0f;

    {
        const uint32_t* Abase = (const uint32_t*)A2 + (r0 + grp) * A2S + q;
        #pragma unroll
        for (int kt = 0; kt < 8; kt++) {
            const int k0 = kt * 8;
            uint32_t a0 = Abase[k0];
            uint32_t a1 = Abase[8 * A2S + k0];
            uint32_t a2 = Abase[k0 + 4];
            uint32_t a3 = Abase[8 * A2S + k0 + 4];
            #pragma unroll
            for (int nt = 0; nt < 8; nt++) {
                uint32_t b0 = w2u[(k0 + q) * WS + nt * 8 + grp];
                uint32_t b1 = w2u[(k0 + 4 + q) * WS + nt * 8 + grp];
                mma_tf32(acc[nt], a0, a1, a2, a3, b0, b1);
            }
        }
    }
    // A1 region is dead here; write without extra barrier
    #pragma unroll
    for (int nt = 0; nt < 8; nt++) {
        float* o = B2 + (r0 + grp) * A2S + nt * 8 + 2 * q;
        *(float2*)o             = make_float2(acc[nt][0], acc[nt][1]);
        *(float2*)(o + 8 * A2S) = make_float2(acc[nt][2], acc[nt][3]);
    }
    __syncthreads();

    // ---- LN3 (width 64) + act, tf32 writeback ----
    #pragma unroll 2
    for (int e = wid; e < TILE; e += 8) {
        float* row = B2 + e * A2S;
        float v0 = row[lane];
        float v1 = row[lane + 32];
        float s = v0 + v1;
        float qq = v0*v0 + v1*v1;
        #pragma unroll
        for (int o = 16; o > 0; o >>= 1) {
            s  += __shfl_xor_sync(0xffffffffu, s, o);
            qq += __shfl_xor_sync(0xffffffffu, qq, o);
        }
        float mu   = s * (1.0f / 64.0f);
        float var  = fmaxf(qq * (1.0f / 64.0f) - mu * mu, 0.0f);
        float rstd = rsqrtf(var + EPSF);
        float h;
        h = (v0 - mu) * rstd * g3s[lane]      + b3s[lane];      row[lane]    = __uint_as_float(f2tf32(h > 0.f ? h : SLOPEF*h));
        h = (v1 - mu) * rstd * g3s[lane + 32] + b3s[lane + 32]; row[lane+32] = __uint_as_float(f2tf32(h > 0.f ? h : SLOPEF*h));
    }
    __syncthreads();

    // ---- GEMM3: msg = B2 @ W3^T, fused segment-max epilogue ----
    #pragma unroll
    for (int nt = 0; nt < 8; nt++)
        #pragma unroll
        for (int j = 0; j < 4; j++) acc[nt][j] = 0.0f;

    {
        const uint32_t* Abase = (const uint32_t*)B2 + (r0 + grp) * A2S + q;
        #pragma unroll
        for (int kt = 0; kt < 8; kt++) {
            const int k0 = kt * 8;
            uint32_t a0 = Abase[k0];
            uint32_t a1 = Abase[8 * A2S + k0];
            uint32_t a2 = Abase[k0 + 4];
            uint32_t a3 = Abase[8 * A2S + k0 + 4];
            #pragma unroll
            for (int nt = 0; nt < 8; nt++) {
                uint32_t b0 = w3u[(k0 + q) * WS + nt * 8 + grp];
                uint32_t b1 = w3u[(k0 + 4 + q) * WS + nt * 8 + grp];
                mma_tf32(acc[nt], a0, a1, a2, a3, b0, b1);
            }
        }
    }

    {
        unsigned* outu = (unsigned*)out;
        const int e_lo = r0 + grp;
        const int e_hi = e_lo + 8;
        const bool ok_lo = (e0 + e_lo) < E;
        const bool ok_hi = (e0 + e_hi) < E;
        const unsigned base_lo = ok_lo ? (unsigned)tgts[e_lo] * HID : 0;
        const unsigned base_hi = ok_hi ? (unsigned)tgts[e_hi] * HID : 0;
        #pragma unroll
        for (int nt = 0; nt < 8; nt++) {
            int c0 = nt * 8 + 2 * q;
            if (ok_lo) {
                atomicMax(outu + base_lo + c0,     fkey(acc[nt][0]));
                atomicMax(outu + base_lo + c0 + 1, fkey(acc[nt][1]));
            }
            if (ok_hi) {
                atomicMax(outu + base_hi + c0,     fkey(acc[nt][2]));
                atomicMax(outu + base_hi + c0 + 1, fkey(acc[nt][3]));
            }
        }
    }
}

extern "C" void kernel_launch(void* const* d_in, const int* in_sizes, int n_in,
                              void* d_out, int out_size) {
    const float* x  = (const float*)d_in[0];
    const float* ew = (const float*)d_in[1];
    const int*   ei = (const int*)d_in[2];
    const float* w1 = (const float*)d_in[3];
    const float* w2 = (const float*)d_in[4];
    const float* w3 = (const float*)d_in[5];
    const float* g1 = (const float*)d_in[6];
    const float* b1 = (const float*)d_in[7];
    const float* g2 = (const float*)d_in[8];
    const float* b2 = (const float*)d_in[9];
    const float* g3 = (const float*)d_in[10];
    const float* b3 = (const float*)d_in[11];
    float* out = (float*)d_out;

    const int E  = in_sizes[1];
    const int NH = out_size;

    cudaFuncSetAttribute(edge_kernel, cudaFuncAttributeMaxDynamicSharedMemorySize, SMEM_BYTES);

    init_kernel<<<(NH + 255) / 256, 256>>>((unsigned*)out, NH);
    edge_kernel<<<(E + TILE - 1) / TILE, NTHR, SMEM_BYTES>>>(
        x, ew, ei, w1, w2, w3, g1, b1, g2, b2, g3, b3, out, E);
    finalize_kernel<<<(NH + 255) / 256, 256>>>(x, out, NH);
}

// round 5
// speedup vs baseline: 2.7212x; 1.0688x over previous
#include <cuda_runtime.h>
#include <math.h>
#include <stdint.h>

#define HID     64
#define TWO_H   128
#define TILE    64
#define NTHR    128
#define EPSF    1e-5f
#define SLOPEF  0.2f

#define WS      72           // weight smem row stride: B-frag banks (8q+grp)%32 conflict-free
#define A1S     132          // m buffer row stride: A-frag banks (4grp+q)%32 conflict-free
#define A2S     68           // h buffer row stride

// shared memory layout (float offsets)
#define OFF_W1  0            // 128*72 = 9216   (GEMM1 weights; A2 overlays after GEMM1)
#define OFF_W2  9216         // 64*72  = 4608
#define OFF_W3  13824        // 64*72  = 4608
#define OFF_A1  18432        // 64*132 = 8448   (m buffer; B2 overlays after GEMM1)
#define OFF_G1  26880
#define OFF_B1  27008
#define OFF_G2  27136
#define OFF_B2  27200
#define OFF_G3  27264
#define OFF_B3  27328
#define OFF_EW  27392
#define OFF_TGT 27456
#define SMEM_FLOATS 27520
#define SMEM_BYTES  (SMEM_FLOATS * 4)   // 110,080 B -> 2 blocks/SM

// monotone float->uint transform: a >= b  <=>  key(a) >= key(b) (unsigned)
__device__ __forceinline__ unsigned fkey(float v) {
    unsigned u = __float_as_uint(v);
    return u ^ (unsigned)(((int)u >> 31) | 0x80000000);
}
#define KEY_NEG_INF 0x007FFFFFu   // key(-inf)

__device__ __forceinline__ uint32_t f2tf32(float f) {
    uint32_t r;
    asm("cvt.rna.tf32.f32 %0, %1;" : "=r"(r) : "f"(f));
    return r;
}

__device__ __forceinline__ void mma_tf32(float acc[4],
                                         uint32_t a0, uint32_t a1, uint32_t a2, uint32_t a3,
                                         uint32_t b0, uint32_t b1) {
    asm volatile(
        "mma.sync.aligned.m16n8k8.row.col.f32.tf32.tf32.f32 "
        "{%0,%1,%2,%3}, {%4,%5,%6,%7}, {%8,%9}, {%0,%1,%2,%3};"
        : "+f"(acc[0]), "+f"(acc[1]), "+f"(acc[2]), "+f"(acc[3])
        : "r"(a0), "r"(a1), "r"(a2), "r"(a3), "r"(b0), "r"(b1));
}

__global__ void init_kernel(uint4* __restrict__ out, int n4) {
    int i = blockIdx.x * blockDim.x + threadIdx.x;
    if (i < n4) out[i] = make_uint4(KEY_NEG_INF, KEY_NEG_INF, KEY_NEG_INF, KEY_NEG_INF);
}

__global__ void finalize_kernel(const float* __restrict__ x, float* __restrict__ out, int n) {
    int i = blockIdx.x * blockDim.x + threadIdx.x;
    if (i < n) {
        unsigned u = ((const unsigned*)out)[i];
        unsigned bits = (u & 0x80000000u) ? (u ^ 0x80000000u) : ~u;
        float v = __uint_as_float(bits);
        if (isinf(v)) v = 0.0f;
        out[i] = v + x[i];
    }
}

__global__ void __launch_bounds__(NTHR, 2)
edge_kernel(const float* __restrict__ x,
            const float* __restrict__ eweight,
            const int* __restrict__ eindex,   // [2, E] int32: row0 src, row1 tgt
            const float* __restrict__ w1,
            const float* __restrict__ w2,
            const float* __restrict__ w3,
            const float* __restrict__ g1, const float* __restrict__ b1,
            const float* __restrict__ g2, const float* __restrict__ b2,
            const float* __restrict__ g3, const float* __restrict__ b3,
            float* __restrict__ out, int E)
{
    extern __shared__ float sm[];
    float*    A1  = sm + OFF_A1;
    uint32_t* w1u = (uint32_t*)(sm + OFF_W1);
    uint32_t* w2u = (uint32_t*)(sm + OFF_W2);
    uint32_t* w3u = (uint32_t*)(sm + OFF_W3);
    float*    A2  = sm + OFF_W1;     // overlays w1 after GEMM1
    float*    B2  = sm + OFF_A1;     // overlays A1 after GEMM1
    float* g1s = sm + OFF_G1;
    float* b1s = sm + OFF_B1;
    float* g2s = sm + OFF_G2;
    float* b2s = sm + OFF_B2;
    float* g3s = sm + OFF_G3;
    float* b3s = sm + OFF_B3;
    float* ews = sm + OFF_EW;
    int*   tgts = (int*)(sm + OFF_TGT);

    const int t    = threadIdx.x;
    const int lane = t & 31;
    const int wid  = t >> 5;          // 0..3
    const int e0   = blockIdx.x * TILE;

    // ---- stage weights transposed + tf32-rounded ----
    for (int i = t; i < 2048; i += NTHR) {          // w1: 64c x 128k
        int c = i & 63, k = (i >> 6) << 2;
        float4 v = *(const float4*)(w1 + c * TWO_H + k);
        w1u[(k + 0) * WS + c] = f2tf32(v.x);
        w1u[(k + 1) * WS + c] = f2tf32(v.y);
        w1u[(k + 2) * WS + c] = f2tf32(v.z);
        w1u[(k + 3) * WS + c] = f2tf32(v.w);
    }
    for (int i = t; i < 1024; i += NTHR) {          // w2, w3: 64c x 64k
        int c = i & 63, k = (i >> 6) << 2;
        float4 v2 = *(const float4*)(w2 + c * HID + k);
        float4 v3 = *(const float4*)(w3 + c * HID + k);
        w2u[(k + 0) * WS + c] = f2tf32(v2.x);
        w2u[(k + 1) * WS + c] = f2tf32(v2.y);
        w2u[(k + 2) * WS + c] = f2tf32(v2.z);
        w2u[(k + 3) * WS + c] = f2tf32(v2.w);
        w3u[(k + 0) * WS + c] = f2tf32(v3.x);
        w3u[(k + 1) * WS + c] = f2tf32(v3.y);
        w3u[(k + 2) * WS + c] = f2tf32(v3.z);
        w3u[(k + 3) * WS + c] = f2tf32(v3.w);
    }
    { g1s[t] = g1[t]; b1s[t] = b1[t]; }
    if (t < 64) { g2s[t] = g2[t]; b2s[t] = b2[t]; g3s[t] = g3[t]; b3s[t] = b3[t]; }
    if (t < TILE) {
        int ge = e0 + t;
        if (ge < E) {
            tgts[t] = eindex[E + ge];
            ews[t]  = eweight[ge];
        } else {
            tgts[t] = 0;
            ews[t]  = 0.0f;
        }
    }
    __syncthreads();

    // ---- build m = [x_i | w*(x_j - x_i)], one thread per (edge, half) ----
    {
        const int r  = t >> 1;
        const int h  = t & 1;
        const int ge = e0 + r;
        float4* dst = (float4*)(A1 + r * A1S + h * 64);
        if (ge < E) {
            int tg = tgts[r];
            const float4* xi = (const float4*)(x + (size_t)tg * HID);
            if (h == 0) {
                #pragma unroll
                for (int f = 0; f < 16; f++) dst[f] = xi[f];
            } else {
                int s = eindex[ge];
                float w = ews[r];
                const float4* xj = (const float4*)(x + (size_t)s * HID);
                #pragma unroll
                for (int f = 0; f < 16; f++) {
                    float4 a = xj[f], b = xi[f];
                    dst[f] = make_float4(w*(a.x-b.x), w*(a.y-b.y), w*(a.z-b.z), w*(a.w-b.w));
                }
            }
        } else {
            #pragma unroll
            for (int f = 0; f < 16; f++) dst[f] = make_float4(0.f,0.f,0.f,0.f);
        }
    }
    __syncthreads();

    // ---- LN1 (width 128) + LeakyReLU, tf32 writeback (warp per row) ----
    #pragma unroll 2
    for (int e = wid; e < TILE; e += 4) {
        float* row = A1 + e * A1S;
        float v0 = row[lane];
        float v1 = row[lane + 32];
        float v2 = row[lane + 64];
        float v3 = row[lane + 96];
        float s = v0 + v1 + v2 + v3;
        float q = v0*v0 + v1*v1 + v2*v2 + v3*v3;
        #pragma unroll
        for (int o = 16; o > 0; o >>= 1) {
            s += __shfl_xor_sync(0xffffffffu, s, o);
            q += __shfl_xor_sync(0xffffffffu, q, o);
        }
        float mu   = s * (1.0f / 128.0f);
        float var  = fmaxf(q * (1.0f / 128.0f) - mu * mu, 0.0f);
        float rstd = rsqrtf(var + EPSF);
        float h;
        h = (v0 - mu) * rstd * g1s[lane]      + b1s[lane];      row[lane]    = __uint_as_float(f2tf32(h > 0.f ? h : SLOPEF*h));
        h = (v1 - mu) * rstd * g1s[lane + 32] + b1s[lane + 32]; row[lane+32] = __uint_as_float(f2tf32(h > 0.f ? h : SLOPEF*h));
        h = (v2 - mu) * rstd * g1s[lane + 64] + b1s[lane + 64]; row[lane+64] = __uint_as_float(f2tf32(h > 0.f ? h : SLOPEF*h));
        h = (v3 - mu) * rstd * g1s[lane + 96] + b1s[lane + 96]; row[lane+96] = __uint_as_float(f2tf32(h > 0.f ? h : SLOPEF*h));
    }
    __syncthreads();

    const int grp = lane >> 2;   // 0..7
    const int q   = lane & 3;    // 0..3
    const int r0  = wid * 16;    // warp's 16-row tile (4 warps x 16 = 64)
    float acc[8][4];

    // ================= GEMM1: A1[64x128] @ W1^T =================
    #pragma unroll
    for (int nt = 0; nt < 8; nt++)
        #pragma unroll
        for (int j = 0; j < 4; j++) acc[nt][j] = 0.0f;
    {
        const uint32_t* Abase = (const uint32_t*)A1 + (r0 + grp) * A1S + q;
        #pragma unroll
        for (int kt = 0; kt < 16; kt++) {
            const int k0 = kt * 8;
            uint32_t a0 = Abase[k0];
            uint32_t a1 = Abase[8 * A1S + k0];
            uint32_t a2 = Abase[k0 + 4];
            uint32_t a3 = Abase[8 * A1S + k0 + 4];
            #pragma unroll
            for (int nt = 0; nt < 8; nt++) {
                uint32_t b0 = w1u[(k0 + q) * WS + nt * 8 + grp];
                uint32_t b1 = w1u[(k0 + 4 + q) * WS + nt * 8 + grp];
                mma_tf32(acc[nt], a0, a1, a2, a3, b0, b1);
            }
        }
    }

    // ---- LN2 in registers (row in a quad: xor 1,2 reduce) ----
    {
        float s_lo = 0.f, q_lo = 0.f, s_hi = 0.f, q_hi = 0.f;
        #pragma unroll
        for (int nt = 0; nt < 8; nt++) {
            s_lo += acc[nt][0] + acc[nt][1];
            q_lo += acc[nt][0]*acc[nt][0] + acc[nt][1]*acc[nt][1];
            s_hi += acc[nt][2] + acc[nt][3];
            q_hi += acc[nt][2]*acc[nt][2] + acc[nt][3]*acc[nt][3];
        }
        #pragma unroll
        for (int o = 1; o <= 2; o <<= 1) {
            s_lo += __shfl_xor_sync(0xffffffffu, s_lo, o);
            q_lo += __shfl_xor_sync(0xffffffffu, q_lo, o);
            s_hi += __shfl_xor_sync(0xffffffffu, s_hi, o);
            q_hi += __shfl_xor_sync(0xffffffffu, q_hi, o);
        }
        float mu_lo = s_lo * (1.0f/64.0f);
        float mu_hi = s_hi * (1.0f/64.0f);
        float r_lo  = rsqrtf(fmaxf(q_lo * (1.0f/64.0f) - mu_lo*mu_lo, 0.0f) + EPSF);
        float r_hi  = rsqrtf(fmaxf(q_hi * (1.0f/64.0f) - mu_hi*mu_hi, 0.0f) + EPSF);

        __syncthreads();   // all warps done reading w1/A1 before A2 overlays w1
        #pragma unroll
        for (int nt = 0; nt < 8; nt++) {
            int c0 = nt * 8 + 2 * q;
            float2 g = *(float2*)(g2s + c0);
            float2 b = *(float2*)(b2s + c0);
            float h0 = (acc[nt][0] - mu_lo) * r_lo * g.x + b.x;
            float h1 = (acc[nt][1] - mu_lo) * r_lo * g.y + b.y;
            float h2 = (acc[nt][2] - mu_hi) * r_hi * g.x + b.x;
            float h3 = (acc[nt][3] - mu_hi) * r_hi * g.y + b.y;
            h0 = h0 > 0.f ? h0 : SLOPEF * h0;
            h1 = h1 > 0.f ? h1 : SLOPEF * h1;
            h2 = h2 > 0.f ? h2 : SLOPEF * h2;
            h3 = h3 > 0.f ? h3 : SLOPEF * h3;
            float* o = A2 + (r0 + grp) * A2S + c0;
            *(float2*)o             = make_float2(__uint_as_float(f2tf32(h0)), __uint_as_float(f2tf32(h1)));
            *(float2*)(o + 8 * A2S) = make_float2(__uint_as_float(f2tf32(h2)), __uint_as_float(f2tf32(h3)));
        }
    }
    __syncthreads();

    // ================= GEMM2: A2[64x64] @ W2^T =================
    #pragma unroll
    for (int nt = 0; nt < 8; nt++)
        #pragma unroll
        for (int j = 0; j < 4; j++) acc[nt][j] = 0.0f;
    {
        const uint32_t* Abase = (const uint32_t*)A2 + (r0 + grp) * A2S + q;
        #pragma unroll
        for (int kt = 0; kt < 8; kt++) {
            const int k0 = kt * 8;
            uint32_t a0 = Abase[k0];
            uint32_t a1 = Abase[8 * A2S + k0];
            uint32_t a2 = Abase[k0 + 4];
            uint32_t a3 = Abase[8 * A2S + k0 + 4];
            #pragma unroll
            for (int nt = 0; nt < 8; nt++) {
                uint32_t b0 = w2u[(k0 + q) * WS + nt * 8 + grp];
                uint32_t b1 = w2u[(k0 + 4 + q) * WS + nt * 8 + grp];
                mma_tf32(acc[nt], a0, a1, a2, a3, b0, b1);
            }
        }
    }

    // ---- LN3 in registers, write B2 (A1 region is dead; no barrier before write) ----
    {
        float s_lo = 0.f, q_lo = 0.f, s_hi = 0.f, q_hi = 0.f;
        #pragma unroll
        for (int nt = 0; nt < 8; nt++) {
            s_lo += acc[nt][0] + acc[nt][1];
            q_lo += acc[nt][0]*acc[nt][0] + acc[nt][1]*acc[nt][1];
            s_hi += acc[nt][2] + acc[nt][3];
            q_hi += acc[nt][2]*acc[nt][2] + acc[nt][3]*acc[nt][3];
        }
        #pragma unroll
        for (int o = 1; o <= 2; o <<= 1) {
            s_lo += __shfl_xor_sync(0xffffffffu, s_lo, o);
            q_lo += __shfl_xor_sync(0xffffffffu, q_lo, o);
            s_hi += __shfl_xor_sync(0xffffffffu, s_hi, o);
            q_hi += __shfl_xor_sync(0xffffffffu, q_hi, o);
        }
        float mu_lo = s_lo * (1.0f/64.0f);
        float mu_hi = s_hi * (1.0f/64.0f);
        float r_lo  = rsqrtf(fmaxf(q_lo * (1.0f/64.0f) - mu_lo*mu_lo, 0.0f) + EPSF);
        float r_hi  = rsqrtf(fmaxf(q_hi * (1.0f/64.0f) - mu_hi*mu_hi, 0.0f) + EPSF);

        #pragma unroll
        for (int nt = 0; nt < 8; nt++) {
            int c0 = nt * 8 + 2 * q;
            float2 g = *(float2*)(g3s + c0);
            float2 b = *(float2*)(b3s + c0);
            float h0 = (acc[nt][0] - mu_lo) * r_lo * g.x + b.x;
            float h1 = (acc[nt][1] - mu_lo) * r_lo * g.y + b.y;
            float h2 = (acc[nt][2] - mu_hi) * r_hi * g.x + b.x;
            float h3 = (acc[nt][3] - mu_hi) * r_hi * g.y + b.y;
            h0 = h0 > 0.f ? h0 : SLOPEF * h0;
            h1 = h1 > 0.f ? h1 : SLOPEF * h1;
            h2 = h2 > 0.f ? h2 : SLOPEF * h2;
            h3 = h3 > 0.f ? h3 : SLOPEF * h3;
            float* o = B2 + (r0 + grp) * A2S + c0;
            *(float2*)o             = make_float2(__uint_as_float(f2tf32(h0)), __uint_as_float(f2tf32(h1)));
            *(float2*)(o + 8 * A2S) = make_float2(__uint_as_float(f2tf32(h2)), __uint_as_float(f2tf32(h3)));
        }
    }
    __syncthreads();

    // ================= GEMM3: B2 @ W3^T + segment-max epilogue =================
    #pragma unroll
    for (int nt = 0; nt < 8; nt++)
        #pragma unroll
        for (int j = 0; j < 4; j++) acc[nt][j] = 0.0f;
    {
        const uint32_t* Abase = (const uint32_t*)B2 + (r0 + grp) * A2S + q;
        #pragma unroll
        for (int kt = 0; kt < 8; kt++) {
            const int k0 = kt * 8;
            uint32_t a0 = Abase[k0];
            uint32_t a1 = Abase[8 * A2S + k0];
            uint32_t a2 = Abase[k0 + 4];
            uint32_t a3 = Abase[8 * A2S + k0 + 4];
            #pragma unroll
            for (int nt = 0; nt < 8; nt++) {
                uint32_t b0 = w3u[(k0 + q) * WS + nt * 8 + grp];
                uint32_t b1 = w3u[(k0 + 4 + q) * WS + nt * 8 + grp];
                mma_tf32(acc[nt], a0, a1, a2, a3, b0, b1);
            }
        }
    }
    {
        unsigned* outu = (unsigned*)out;
        const int e_lo = r0 + grp;
        const int e_hi = e_lo + 8;
        const bool ok_lo = (e0 + e_lo) < E;
        const bool ok_hi = (e0 + e_hi) < E;
        const unsigned base_lo = ok_lo ? (unsigned)tgts[e_lo] * HID : 0;
        const unsigned base_hi = ok_hi ? (unsigned)tgts[e_hi] * HID : 0;
        #pragma unroll
        for (int nt = 0; nt < 8; nt++) {
            int c0 = nt * 8 + 2 * q;
            if (ok_lo) {
                atomicMax(outu + base_lo + c0,     fkey(acc[nt][0]));
                atomicMax(outu + base_lo + c0 + 1, fkey(acc[nt][1]));
            }
            if (ok_hi) {
                atomicMax(outu + base_hi + c0,     fkey(acc[nt][2]));
                atomicMax(outu + base_hi + c0 + 1, fkey(acc[nt][3]));
            }
        }
    }
}

extern "C" void kernel_launch(void* const* d_in, const int* in_sizes, int n_in,
                              void* d_out, int out_size) {
    const float* x  = (const float*)d_in[0];
    const float* ew = (const float*)d_in[1];
    const int*   ei = (const int*)d_in[2];
    const float* w1 = (const float*)d_in[3];
    const float* w2 = (const float*)d_in[4];
    const float* w3 = (const float*)d_in[5];
    const float* g1 = (const float*)d_in[6];
    const float* b1 = (const float*)d_in[7];
    const float* g2 = (const float*)d_in[8];
    const float* b2 = (const float*)d_in[9];
    const float* g3 = (const float*)d_in[10];
    const float* b3 = (const float*)d_in[11];
    float* out = (float*)d_out;

    const int E  = in_sizes[1];
    const int NH = out_size;

    cudaFuncSetAttribute(edge_kernel, cudaFuncAttributeMaxDynamicSharedMemorySize, SMEM_BYTES);

    init_kernel<<<(NH/4 + 255) / 256, 256>>>((uint4*)out, NH / 4);
    edge_kernel<<<(E + TILE - 1) / TILE, NTHR, SMEM_BYTES>>>(
        x, ew, ei, w1, w2, w3, g1, b1, g2, b2, g3, b3, out, E);
    finalize_kernel<<<(NH + 255) / 256, 256>>>(x, out, NH);
}

// round 6
// speedup vs baseline: 5.1202x; 1.8816x over previous
#include <cuda_runtime.h>
#include <math.h>
#include <stdint.h>

#define HID     64
#define TWO_H   128
#define TILE    128
#define NTHR    256
#define EPSF    1e-5f
#define SLOPEF  0.2f

#define WS      72           // weight smem row stride: B-frag banks (8q+grp)%32 conflict-free
#define A2S     68           // activation buffer row stride

// shared memory layout (float offsets)
#define OFF_W1  0            // 128*72 = 9216 ; A2 overlays this after GEMM1
#define OFF_W2  9216         // 64*72  = 4608
#define OFF_W3  13824        // 64*72  = 4608
#define OFF_HB  18432        // 128*68 = 8704 (B2 buffer for GEMM3 A-operand)
#define OFF_G1  27136
#define OFF_B1  27264
#define OFF_G2  27392
#define OFF_BB2 27456
#define OFF_G3  27520
#define OFF_BB3 27584
#define OFF_EW  27648
#define OFF_TGT 27776
#define SMEM_FLOATS 27904
#define SMEM_BYTES  (SMEM_FLOATS * 4)   // 111,616 B -> 2 blocks/SM

// monotone float->uint transform: a >= b  <=>  key(a) >= key(b) (unsigned)
__device__ __forceinline__ unsigned fkey(float v) {
    unsigned u = __float_as_uint(v);
    return u ^ (unsigned)(((int)u >> 31) | 0x80000000);
}
#define KEY_NEG_INF 0x007FFFFFu   // key(-inf)

__device__ __forceinline__ uint32_t f2tf32(float f) {
    uint32_t r;
    asm("cvt.rna.tf32.f32 %0, %1;" : "=r"(r) : "f"(f));
    return r;
}

__device__ __forceinline__ void mma_tf32(float acc[4],
                                         uint32_t a0, uint32_t a1, uint32_t a2, uint32_t a3,
                                         uint32_t b0, uint32_t b1) {
    asm volatile(
        "mma.sync.aligned.m16n8k8.row.col.f32.tf32.tf32.f32 "
        "{%0,%1,%2,%3}, {%4,%5,%6,%7}, {%8,%9}, {%0,%1,%2,%3};"
        : "+f"(acc[0]), "+f"(acc[1]), "+f"(acc[2]), "+f"(acc[3])
        : "r"(a0), "r"(a1), "r"(a2), "r"(a3), "r"(b0), "r"(b1));
}

__global__ void init_kernel(uint4* __restrict__ out, int n4) {
    int i = blockIdx.x * blockDim.x + threadIdx.x;
    if (i < n4) out[i] = make_uint4(KEY_NEG_INF, KEY_NEG_INF, KEY_NEG_INF, KEY_NEG_INF);
}

__global__ void finalize_kernel(const float* __restrict__ x, float* __restrict__ out, int n) {
    int i = blockIdx.x * blockDim.x + threadIdx.x;
    if (i < n) {
        unsigned u = ((const unsigned*)out)[i];
        unsigned bits = (u & 0x80000000u) ? (u ^ 0x80000000u) : ~u;
        float v = __uint_as_float(bits);
        if (isinf(v)) v = 0.0f;
        out[i] = v + x[i];
    }
}

__global__ void __launch_bounds__(NTHR, 2)
edge_kernel(const float* __restrict__ x,
            const float* __restrict__ eweight,
            const int* __restrict__ eindex,   // [2, E] int32: row0 src, row1 tgt
            const float* __restrict__ w1,
            const float* __restrict__ w2,
            const float* __restrict__ w3,
            const float* __restrict__ g1, const float* __restrict__ b1,
            const float* __restrict__ g2, const float* __restrict__ b2,
            const float* __restrict__ g3, const float* __restrict__ b3,
            float* __restrict__ out, int E)
{
    extern __shared__ float sm[];
    uint32_t* w1u = (uint32_t*)(sm + OFF_W1);
    uint32_t* w2u = (uint32_t*)(sm + OFF_W2);
    uint32_t* w3u = (uint32_t*)(sm + OFF_W3);
    float*    A2  = sm + OFF_W1;     // overlays w1 after GEMM1
    float*    HB  = sm + OFF_HB;     // GEMM3 A-operand
    float* g1s = sm + OFF_G1;
    float* b1s = sm + OFF_B1;
    float* g2s = sm + OFF_G2;
    float* b2s = sm + OFF_BB2;
    float* g3s = sm + OFF_G3;
    float* b3s = sm + OFF_BB3;
    float* ews = sm + OFF_EW;
    int*   tgts = (int*)(sm + OFF_TGT);

    const int t    = threadIdx.x;
    const int lane = t & 31;
    const int wid  = t >> 5;          // 0..7
    const int e0   = blockIdx.x * TILE;

    // ---- stage weights transposed + tf32-rounded ----
    for (int i = t; i < 2048; i += NTHR) {          // w1: 64c x 128k
        int c = i & 63, k = (i >> 6) << 2;
        float4 v = *(const float4*)(w1 + c * TWO_H + k);
        w1u[(k + 0) * WS + c] = f2tf32(v.x);
        w1u[(k + 1) * WS + c] = f2tf32(v.y);
        w1u[(k + 2) * WS + c] = f2tf32(v.z);
        w1u[(k + 3) * WS + c] = f2tf32(v.w);
    }
    for (int i = t; i < 1024; i += NTHR) {          // w2, w3: 64c x 64k
        int c = i & 63, k = (i >> 6) << 2;
        float4 v2 = *(const float4*)(w2 + c * HID + k);
        float4 v3 = *(const float4*)(w3 + c * HID + k);
        w2u[(k + 0) * WS + c] = f2tf32(v2.x);
        w2u[(k + 1) * WS + c] = f2tf32(v2.y);
        w2u[(k + 2) * WS + c] = f2tf32(v2.z);
        w2u[(k + 3) * WS + c] = f2tf32(v2.w);
        w3u[(k + 0) * WS + c] = f2tf32(v3.x);
        w3u[(k + 1) * WS + c] = f2tf32(v3.y);
        w3u[(k + 2) * WS + c] = f2tf32(v3.z);
        w3u[(k + 3) * WS + c] = f2tf32(v3.w);
    }
    if (t < 128) { g1s[t] = g1[t]; b1s[t] = b1[t]; }
    else if (t < 192) {
        int u = t - 128;
        g2s[u] = g2[u]; b2s[u] = b2[u]; g3s[u] = g3[u]; b3s[u] = b3[u];
    }
    if (t < TILE) {
        int ge = e0 + t;
        if (ge < E) {
            tgts[t] = eindex[E + ge];
            ews[t]  = eweight[ge];
        } else {
            tgts[t] = 0;
            ews[t]  = 0.0f;
        }
    }
    __syncthreads();

    const int grp  = lane >> 2;     // 0..7
    const int q    = lane & 3;      // 0..3
    const int r0   = wid * 16;      // warp's 16-row tile (8 warps x 16 = 128)
    const int r_lo = r0 + grp;
    const int r_hi = r_lo + 8;

    // ---- gather m-fragments straight into registers ----
    // mlo[tt]/mhi[tt] hold m[row][q + 4*tt]: tt 0..15 -> x_i half, 16..31 -> diff half
    float mlo[32], mhi[32];
    {
        int ge = e0 + r_lo;
        if (ge < E) {
            const float* xi = x + (size_t)tgts[r_lo] * HID;
            const float* xj = x + (size_t)eindex[ge] * HID;
            float w = ews[r_lo];
            #pragma unroll
            for (int tt = 0; tt < 16; tt++) {
                int c = q + 4 * tt;
                float vi = __ldg(xi + c);
                float vj = __ldg(xj + c);
                mlo[tt]      = vi;
                mlo[16 + tt] = w * (vj - vi);
            }
        } else {
            #pragma unroll
            for (int tt = 0; tt < 32; tt++) mlo[tt] = 0.0f;
        }
    }
    {
        int ge = e0 + r_hi;
        if (ge < E) {
            const float* xi = x + (size_t)tgts[r_hi] * HID;
            const float* xj = x + (size_t)eindex[ge] * HID;
            float w = ews[r_hi];
            #pragma unroll
            for (int tt = 0; tt < 16; tt++) {
                int c = q + 4 * tt;
                float vi = __ldg(xi + c);
                float vj = __ldg(xj + c);
                mhi[tt]      = vi;
                mhi[16 + tt] = w * (vj - vi);
            }
        } else {
            #pragma unroll
            for (int tt = 0; tt < 32; tt++) mhi[tt] = 0.0f;
        }
    }

    // ---- LN1 (width 128) in registers: quad holds the full row ----
    {
        float s_lo = 0.f, q_lo = 0.f, s_hi = 0.f, q_hi = 0.f;
        #pragma unroll
        for (int tt = 0; tt < 32; tt++) {
            s_lo += mlo[tt]; q_lo += mlo[tt] * mlo[tt];
            s_hi += mhi[tt]; q_hi += mhi[tt] * mhi[tt];
        }
        #pragma unroll
        for (int o = 1; o <= 2; o <<= 1) {
            s_lo += __shfl_xor_sync(0xffffffffu, s_lo, o);
            q_lo += __shfl_xor_sync(0xffffffffu, q_lo, o);
            s_hi += __shfl_xor_sync(0xffffffffu, s_hi, o);
            q_hi += __shfl_xor_sync(0xffffffffu, q_hi, o);
        }
        float mu_lo = s_lo * (1.0f / 128.0f);
        float mu_hi = s_hi * (1.0f / 128.0f);
        float r_l   = rsqrtf(fmaxf(q_lo * (1.0f / 128.0f) - mu_lo * mu_lo, 0.0f) + EPSF);
        float r_h   = rsqrtf(fmaxf(q_hi * (1.0f / 128.0f) - mu_hi * mu_hi, 0.0f) + EPSF);
        #pragma unroll
        for (int tt = 0; tt < 32; tt++) {
            int c = q + 4 * tt;
            float g = g1s[c], b = b1s[c];
            float h0 = (mlo[tt] - mu_lo) * r_l * g + b;
            float h1 = (mhi[tt] - mu_hi) * r_h * g + b;
            h0 = h0 > 0.f ? h0 : SLOPEF * h0;
            h1 = h1 > 0.f ? h1 : SLOPEF * h1;
            mlo[tt] = __uint_as_float(f2tf32(h0));
            mhi[tt] = __uint_as_float(f2tf32(h1));
        }
    }

    float acc[8][4];

    // ================= GEMM1: m[128x128] @ W1^T (A from registers) =================
    #pragma unroll
    for (int nt = 0; nt < 8; nt++)
        #pragma unroll
        for (int j = 0; j < 4; j++) acc[nt][j] = 0.0f;
    #pragma unroll
    for (int kt = 0; kt < 16; kt++) {
        const int k0 = kt * 8;
        uint32_t a0 = __float_as_uint(mlo[2 * kt]);
        uint32_t a1 = __float_as_uint(mhi[2 * kt]);
        uint32_t a2 = __float_as_uint(mlo[2 * kt + 1]);
        uint32_t a3 = __float_as_uint(mhi[2 * kt + 1]);
        #pragma unroll
        for (int nt = 0; nt < 8; nt++) {
            uint32_t b0 = w1u[(k0 + q) * WS + nt * 8 + grp];
            uint32_t b1 = w1u[(k0 + 4 + q) * WS + nt * 8 + grp];
            mma_tf32(acc[nt], a0, a1, a2, a3, b0, b1);
        }
    }

    // ---- LN2 in registers, write A2 (overlays w1) ----
    {
        float s_lo = 0.f, q_lo = 0.f, s_hi = 0.f, q_hi = 0.f;
        #pragma unroll
        for (int nt = 0; nt < 8; nt++) {
            s_lo += acc[nt][0] + acc[nt][1];
            q_lo += acc[nt][0]*acc[nt][0] + acc[nt][1]*acc[nt][1];
            s_hi += acc[nt][2] + acc[nt][3];
            q_hi += acc[nt][2]*acc[nt][2] + acc[nt][3]*acc[nt][3];
        }
        #pragma unroll
        for (int o = 1; o <= 2; o <<= 1) {
            s_lo += __shfl_xor_sync(0xffffffffu, s_lo, o);
            q_lo += __shfl_xor_sync(0xffffffffu, q_lo, o);
            s_hi += __shfl_xor_sync(0xffffffffu, s_hi, o);
            q_hi += __shfl_xor_sync(0xffffffffu, q_hi, o);
        }
        float mu_lo = s_lo * (1.0f/64.0f);
        float mu_hi = s_hi * (1.0f/64.0f);
        float r_l   = rsqrtf(fmaxf(q_lo * (1.0f/64.0f) - mu_lo*mu_lo, 0.0f) + EPSF);
        float r_h   = rsqrtf(fmaxf(q_hi * (1.0f/64.0f) - mu_hi*mu_hi, 0.0f) + EPSF);

        __syncthreads();   // all warps done reading w1u before A2 overlays it
        #pragma unroll
        for (int nt = 0; nt < 8; nt++) {
            int c0 = nt * 8 + 2 * q;
            float2 g = *(float2*)(g2s + c0);
            float2 b = *(float2*)(b2s + c0);
            float h0 = (acc[nt][0] - mu_lo) * r_l * g.x + b.x;
            float h1 = (acc[nt][1] - mu_lo) * r_l * g.y + b.y;
            float h2 = (acc[nt][2] - mu_hi) * r_h * g.x + b.x;
            float h3 = (acc[nt][3] - mu_hi) * r_h * g.y + b.y;
            h0 = h0 > 0.f ? h0 : SLOPEF * h0;
            h1 = h1 > 0.f ? h1 : SLOPEF * h1;
            h2 = h2 > 0.f ? h2 : SLOPEF * h2;
            h3 = h3 > 0.f ? h3 : SLOPEF * h3;
            float* o = A2 + r_lo * A2S + c0;
            *(float2*)o             = make_float2(__uint_as_float(f2tf32(h0)), __uint_as_float(f2tf32(h1)));
            *(float2*)(o + 8 * A2S) = make_float2(__uint_as_float(f2tf32(h2)), __uint_as_float(f2tf32(h3)));
        }
    }
    __syncwarp();   // rows are warp-private; warp-level ordering suffices

    // ================= GEMM2: A2[128x64] @ W2^T =================
    #pragma unroll
    for (int nt = 0; nt < 8; nt++)
        #pragma unroll
        for (int j = 0; j < 4; j++) acc[nt][j] = 0.0f;
    {
        const uint32_t* Abase = (const uint32_t*)A2 + r_lo * A2S + q;
        #pragma unroll
        for (int kt = 0; kt < 8; kt++) {
            const int k0 = kt * 8;
            uint32_t a0 = Abase[k0];
            uint32_t a1 = Abase[8 * A2S + k0];
            uint32_t a2 = Abase[k0 + 4];
            uint32_t a3 = Abase[8 * A2S + k0 + 4];
            #pragma unroll
            for (int nt = 0; nt < 8; nt++) {
                uint32_t b0 = w2u[(k0 + q) * WS + nt * 8 + grp];
                uint32_t b1 = w2u[(k0 + 4 + q) * WS + nt * 8 + grp];
                mma_tf32(acc[nt], a0, a1, a2, a3, b0, b1);
            }
        }
    }

    // ---- LN3 in registers, write HB (separate buffer, warp-private rows) ----
    {
        float s_lo = 0.f, q_lo = 0.f, s_hi = 0.f, q_hi = 0.f;
        #pragma unroll
        for (int nt = 0; nt < 8; nt++) {
            s_lo += acc[nt][0] + acc[nt][1];
            q_lo += acc[nt][0]*acc[nt][0] + acc[nt][1]*acc[nt][1];
            s_hi += acc[nt][2] + acc[nt][3];
            q_hi += acc[nt][2]*acc[nt][2] + acc[nt][3]*acc[nt][3];
        }
        #pragma unroll
        for (int o = 1; o <= 2; o <<= 1) {
            s_lo += __shfl_xor_sync(0xffffffffu, s_lo, o);
            q_lo += __shfl_xor_sync(0xffffffffu, q_lo, o);
            s_hi += __shfl_xor_sync(0xffffffffu, s_hi, o);
            q_hi += __shfl_xor_sync(0xffffffffu, q_hi, o);
        }
        float mu_lo = s_lo * (1.0f/64.0f);
        float mu_hi = s_hi * (1.0f/64.0f);
        float r_l   = rsqrtf(fmaxf(q_lo * (1.0f/64.0f) - mu_lo*mu_lo, 0.0f) + EPSF);
        float r_h   = rsqrtf(fmaxf(q_hi * (1.0f/64.0f) - mu_hi*mu_hi, 0.0f) + EPSF);

        #pragma unroll
        for (int nt = 0; nt < 8; nt++) {
            int c0 = nt * 8 + 2 * q;
            float2 g = *(float2*)(g3s + c0);
            float2 b = *(float2*)(b3s + c0);
            float h0 = (acc[nt][0] - mu_lo) * r_l * g.x + b.x;
            float h1 = (acc[nt][1] - mu_lo) * r_l * g.y + b.y;
            float h2 = (acc[nt][2] - mu_hi) * r_h * g.x + b.x;
            float h3 = (acc[nt][3] - mu_hi) * r_h * g.y + b.y;
            h0 = h0 > 0.f ? h0 : SLOPEF * h0;
            h1 = h1 > 0.f ? h1 : SLOPEF * h1;
            h2 = h2 > 0.f ? h2 : SLOPEF * h2;
            h3 = h3 > 0.f ? h3 : SLOPEF * h3;
            float* o = HB + r_lo * A2S + c0;
            *(float2*)o             = make_float2(__uint_as_float(f2tf32(h0)), __uint_as_float(f2tf32(h1)));
            *(float2*)(o + 8 * A2S) = make_float2(__uint_as_float(f2tf32(h2)), __uint_as_float(f2tf32(h3)));
        }
    }
    __syncwarp();

    // ================= GEMM3: HB @ W3^T + segment-max epilogue =================
    #pragma unroll
    for (int nt = 0; nt < 8; nt++)
        #pragma unroll
        for (int j = 0; j < 4; j++) acc[nt][j] = 0.0f;
    {
        const uint32_t* Abase = (const uint32_t*)HB + r_lo * A2S + q;
        #pragma unroll
        for (int kt = 0; kt < 8; kt++) {
            const int k0 = kt * 8;
            uint32_t a0 = Abase[k0];
            uint32_t a1 = Abase[8 * A2S + k0];
            uint32_t a2 = Abase[k0 + 4];
            uint32_t a3 = Abase[8 * A2S + k0 + 4];
            #pragma unroll
            for (int nt = 0; nt < 8; nt++) {
                uint32_t b0 = w3u[(k0 + q) * WS + nt * 8 + grp];
                uint32_t b1 = w3u[(k0 + 4 + q) * WS + nt * 8 + grp];
                mma_tf32(acc[nt], a0, a1, a2, a3, b0, b1);
            }
        }
    }
    {
        unsigned* outu = (unsigned*)out;
        const bool ok_lo = (e0 + r_lo) < E;
        const bool ok_hi = (e0 + r_hi) < E;
        const unsigned base_lo = ok_lo ? (unsigned)tgts[r_lo] * HID : 0;
        const unsigned base_hi = ok_hi ? (unsigned)tgts[r_hi] * HID : 0;
        #pragma unroll
        for (int nt = 0; nt < 8; nt++) {
            int c0 = nt * 8 + 2 * q;
            if (ok_lo) {
                atomicMax(outu + base_lo + c0,     fkey(acc[nt][0]));
                atomicMax(outu + base_lo + c0 + 1, fkey(acc[nt][1]));
            }
            if (ok_hi) {
                atomicMax(outu + base_hi + c0,     fkey(acc[nt][2]));
                atomicMax(outu + base_hi + c0 + 1, fkey(acc[nt][3]));
            }
        }
    }
}

extern "C" void kernel_launch(void* const* d_in, const int* in_sizes, int n_in,
                              void* d_out, int out_size) {
    const float* x  = (const float*)d_in[0];
    const float* ew = (const float*)d_in[1];
    const int*   ei = (const int*)d_in[2];
    const float* w1 = (const float*)d_in[3];
    const float* w2 = (const float*)d_in[4];
    const float* w3 = (const float*)d_in[5];
    const float* g1 = (const float*)d_in[6];
    const float* b1 = (const float*)d_in[7];
    const float* g2 = (const float*)d_in[8];
    const float* b2 = (const float*)d_in[9];
    const float* g3 = (const float*)d_in[10];
    const float* b3 = (const float*)d_in[11];
    float* out = (float*)d_out;

    const int E  = in_sizes[1];
    const int NH = out_size;

    cudaFuncSetAttribute(edge_kernel, cudaFuncAttributeMaxDynamicSharedMemorySize, SMEM_BYTES);

    init_kernel<<<(NH/4 + 255) / 256, 256>>>((uint4*)out, NH / 4);
    edge_kernel<<<(E + TILE - 1) / TILE, NTHR, SMEM_BYTES>>>(
        x, ew, ei, w1, w2, w3, g1, b1, g2, b2, g3, b3, out, E);
    finalize_kernel<<<(NH + 255) / 256, 256>>>(x, out, NH);
}

// round 7
// speedup vs baseline: 5.3964x; 1.0539x over previous
#include <cuda_runtime.h>
#include <math.h>
#include <stdint.h>

#define HID     64
#define TWO_H   128
#define TILE    128
#define NTHR    256
#define EPSF    1e-5f
#define SLOPEF  0.2f

#define WS      72           // weight smem row stride: B-frag banks conflict-free
#define A2S     68           // activation buffer row stride

// shared memory layout (float offsets)
#define OFF_W1  0            // 9216 ; A2 overlays after GEMM1; MS overlays for epilogue
#define OFF_W2  9216         // 4608
#define OFF_W3  13824        // 4608
#define OFF_HB  18432        // 8704
#define OFF_G1  27136
#define OFF_B1  27264
#define OFF_G2  27392
#define OFF_BB2 27456
#define OFF_G3  27520
#define OFF_BB3 27584
#define OFF_EW  27648
#define OFF_TGT 27776
#define OFF_EID 27904
#define SMEM_FLOATS 28032
#define SMEM_BYTES  (SMEM_FLOATS * 4)   // 112,128 B -> 2 blocks/SM

// -------- sort scratch (device globals; no runtime allocation) --------
#define MAXN 262145          // supports N+1 up to this
#define MAXE 1048576
__device__ int d_cnt[MAXN + 1];
__device__ int d_part[256];
__device__ int d_sorted[MAXE];

// monotone float->uint transform: a >= b  <=>  key(a) >= key(b) (unsigned)
__device__ __forceinline__ unsigned fkey(float v) {
    unsigned u = __float_as_uint(v);
    return u ^ (unsigned)(((int)u >> 31) | 0x80000000);
}
#define KEY_NEG_INF 0x007FFFFFu
#define NEG_INF_F   __int_as_float(0xFF800000)

__device__ __forceinline__ uint32_t f2tf32(float f) {
    uint32_t r;
    asm("cvt.rna.tf32.f32 %0, %1;" : "=r"(r) : "f"(f));
    return r;
}

__device__ __forceinline__ void mma_tf32(float acc[4],
                                         uint32_t a0, uint32_t a1, uint32_t a2, uint32_t a3,
                                         uint32_t b0, uint32_t b1) {
    asm volatile(
        "mma.sync.aligned.m16n8k8.row.col.f32.tf32.tf32.f32 "
        "{%0,%1,%2,%3}, {%4,%5,%6,%7}, {%8,%9}, {%0,%1,%2,%3};"
        : "+f"(acc[0]), "+f"(acc[1]), "+f"(acc[2]), "+f"(acc[3])
        : "r"(a0), "r"(a1), "r"(a2), "r"(a3), "r"(b0), "r"(b1));
}

// ======================= sort-by-target kernels =======================
__global__ void zero_cnt_kernel(int n) {
    int i = blockIdx.x * blockDim.x + threadIdx.x;
    if (i < n) d_cnt[i] = 0;
}

__global__ void hist_kernel(const int* __restrict__ eindex, int E) {
    int i = blockIdx.x * blockDim.x + threadIdx.x;
    if (i < E) atomicAdd(&d_cnt[eindex[E + i] + 1], 1);
}

// inclusive scan of 1024-element chunk; writes chunk total to d_part[bid]
__global__ void scan_chunk_kernel(int n) {
    __shared__ int wsum[8];
    int t = threadIdx.x, lane = t & 31, w = t >> 5;
    int base = blockIdx.x * 1024 + t * 4;
    int v0 = 0, v1 = 0, v2 = 0, v3 = 0;
    if (base + 3 < n) { int4 qv = *(const int4*)(d_cnt + base); v0 = qv.x; v1 = qv.y; v2 = qv.z; v3 = qv.w; }
    else {
        if (base     < n) v0 = d_cnt[base];
        if (base + 1 < n) v1 = d_cnt[base + 1];
        if (base + 2 < n) v2 = d_cnt[base + 2];
        if (base + 3 < n) v3 = d_cnt[base + 3];
    }
    v1 += v0; v2 += v1; v3 += v2;
    int s = v3;
    #pragma unroll
    for (int o = 1; o < 32; o <<= 1) {
        int u = __shfl_up_sync(0xffffffffu, s, o);
        if (lane >= o) s += u;
    }
    if (lane == 31) wsum[w] = s;
    __syncthreads();
    if (w == 0) {
        int ws = (lane < 8) ? wsum[lane] : 0;
        #pragma unroll
        for (int o = 1; o < 8; o <<= 1) {
            int u = __shfl_up_sync(0xffffffffu, ws, o);
            if (lane >= o) ws += u;
        }
        if (lane < 8) wsum[lane] = ws;
    }
    __syncthreads();
    int excl = s - v3 + (w > 0 ? wsum[w - 1] : 0);
    if (base + 3 < n) {
        int4 qv; qv.x = v0 + excl; qv.y = v1 + excl; qv.z = v2 + excl; qv.w = v3 + excl;
        *(int4*)(d_cnt + base) = qv;
    } else {
        if (base     < n) d_cnt[base]     = v0 + excl;
        if (base + 1 < n) d_cnt[base + 1] = v1 + excl;
        if (base + 2 < n) d_cnt[base + 2] = v2 + excl;
        if (base + 3 < n) d_cnt[base + 3] = v3 + excl;
    }
    if (t == 255) d_part[blockIdx.x] = wsum[7];
}

__global__ void scan_part_kernel(int np) {
    __shared__ int sh[256];
    int t = threadIdx.x;
    sh[t] = (t < np) ? d_part[t] : 0;
    __syncthreads();
    #pragma unroll
    for (int o = 1; o < 256; o <<= 1) {
        int v = (t >= o) ? sh[t - o] : 0;
        __syncthreads();
        sh[t] += v;
        __syncthreads();
    }
    if (t < np) d_part[t] = (t == 0) ? 0 : sh[t - 1];   // exclusive
}

__global__ void add_part_kernel(int n) {
    if (blockIdx.x == 0) return;
    int add = d_part[blockIdx.x];
    int base = blockIdx.x * 1024 + threadIdx.x * 4;
    #pragma unroll
    for (int j = 0; j < 4; j++)
        if (base + j < n) d_cnt[base + j] += add;
}

__global__ void scatter_kernel(const int* __restrict__ eindex, int E) {
    int i = blockIdx.x * blockDim.x + threadIdx.x;
    if (i < E) {
        int tg = eindex[E + i];
        int pos = atomicAdd(&d_cnt[tg], 1);
        d_sorted[pos] = i;
    }
}

// ======================= output init / finalize =======================
__global__ void init_kernel(uint4* __restrict__ out, int n4) {
    int i = blockIdx.x * blockDim.x + threadIdx.x;
    if (i < n4) out[i] = make_uint4(KEY_NEG_INF, KEY_NEG_INF, KEY_NEG_INF, KEY_NEG_INF);
}

__global__ void finalize_kernel(const float* __restrict__ x, float* __restrict__ out, int n) {
    int i = blockIdx.x * blockDim.x + threadIdx.x;
    if (i < n) {
        unsigned u = ((const unsigned*)out)[i];
        unsigned bits = (u & 0x80000000u) ? (u ^ 0x80000000u) : ~u;
        float v = __uint_as_float(bits);
        if (isinf(v)) v = 0.0f;
        out[i] = v + x[i];
    }
}

// ======================= main edge kernel =======================
__global__ void __launch_bounds__(NTHR, 2)
edge_kernel(const float* __restrict__ x,
            const float* __restrict__ eweight,
            const int* __restrict__ eindex,   // [2, E] int32: row0 src, row1 tgt
            const float* __restrict__ w1,
            const float* __restrict__ w2,
            const float* __restrict__ w3,
            const float* __restrict__ g1, const float* __restrict__ b1,
            const float* __restrict__ g2, const float* __restrict__ b2,
            const float* __restrict__ g3, const float* __restrict__ b3,
            float* __restrict__ out, int E)
{
    extern __shared__ float sm[];
    uint32_t* w1u = (uint32_t*)(sm + OFF_W1);
    uint32_t* w2u = (uint32_t*)(sm + OFF_W2);
    uint32_t* w3u = (uint32_t*)(sm + OFF_W3);
    float*    A2  = sm + OFF_W1;     // overlays w1 after GEMM1
    float*    MS  = sm + OFF_W1;     // message staging for epilogue (same region)
    float*    HB  = sm + OFF_HB;
    float* g1s = sm + OFF_G1;
    float* b1s = sm + OFF_B1;
    float* g2s = sm + OFF_G2;
    float* b2s = sm + OFF_BB2;
    float* g3s = sm + OFF_G3;
    float* b3s = sm + OFF_BB3;
    float* ews = sm + OFF_EW;
    int*   tgts = (int*)(sm + OFF_TGT);
    int*   eids = (int*)(sm + OFF_EID);

    const int t    = threadIdx.x;
    const int lane = t & 31;
    const int wid  = t >> 5;          // 0..7
    const int e0   = blockIdx.x * TILE;

    // ---- stage weights transposed + tf32-rounded ----
    for (int i = t; i < 2048; i += NTHR) {          // w1: 64c x 128k
        int c = i & 63, k = (i >> 6) << 2;
        float4 v = *(const float4*)(w1 + c * TWO_H + k);
        w1u[(k + 0) * WS + c] = f2tf32(v.x);
        w1u[(k + 1) * WS + c] = f2tf32(v.y);
        w1u[(k + 2) * WS + c] = f2tf32(v.z);
        w1u[(k + 3) * WS + c] = f2tf32(v.w);
    }
    for (int i = t; i < 1024; i += NTHR) {          // w2, w3: 64c x 64k
        int c = i & 63, k = (i >> 6) << 2;
        float4 v2 = *(const float4*)(w2 + c * HID + k);
        float4 v3 = *(const float4*)(w3 + c * HID + k);
        w2u[(k + 0) * WS + c] = f2tf32(v2.x);
        w2u[(k + 1) * WS + c] = f2tf32(v2.y);
        w2u[(k + 2) * WS + c] = f2tf32(v2.z);
        w2u[(k + 3) * WS + c] = f2tf32(v2.w);
        w3u[(k + 0) * WS + c] = f2tf32(v3.x);
        w3u[(k + 1) * WS + c] = f2tf32(v3.y);
        w3u[(k + 2) * WS + c] = f2tf32(v3.z);
        w3u[(k + 3) * WS + c] = f2tf32(v3.w);
    }
    if (t < 128) { g1s[t] = g1[t]; b1s[t] = b1[t]; }
    else if (t < 192) {
        int u = t - 128;
        g2s[u] = g2[u]; b2s[u] = b2[u]; g3s[u] = g3[u]; b3s[u] = b3[u];
    }
    if (t < TILE) {
        int ge = e0 + t;
        int eid = (ge < E) ? d_sorted[ge] : -1;
        eids[t] = eid;
        if (eid >= 0) {
            tgts[t] = eindex[E + eid];
            ews[t]  = eweight[eid];
        } else {
            tgts[t] = -1;
            ews[t]  = 0.0f;
        }
    }
    __syncthreads();

    const int grp  = lane >> 2;     // 0..7
    const int q    = lane & 3;      // 0..3
    const int r0   = wid * 16;      // warp's 16 consecutive sorted rows
    const int r_lo = r0 + grp;
    const int r_hi = r_lo + 8;

    // ---- gather m-fragments straight into registers ----
    float mlo[32], mhi[32];
    {
        int eid = eids[r_lo];
        if (eid >= 0) {
            const float* xi = x + (size_t)tgts[r_lo] * HID;
            const float* xj = x + (size_t)eindex[eid] * HID;
            float w = ews[r_lo];
            #pragma unroll
            for (int tt = 0; tt < 16; tt++) {
                int c = q + 4 * tt;
                float vi = __ldg(xi + c);
                float vj = __ldg(xj + c);
                mlo[tt]      = vi;
                mlo[16 + tt] = w * (vj - vi);
            }
        } else {
            #pragma unroll
            for (int tt = 0; tt < 32; tt++) mlo[tt] = 0.0f;
        }
    }
    {
        int eid = eids[r_hi];
        if (eid >= 0) {
            const float* xi = x + (size_t)tgts[r_hi] * HID;
            const float* xj = x + (size_t)eindex[eid] * HID;
            float w = ews[r_hi];
            #pragma unroll
            for (int tt = 0; tt < 16; tt++) {
                int c = q + 4 * tt;
                float vi = __ldg(xi + c);
                float vj = __ldg(xj + c);
                mhi[tt]      = vi;
                mhi[16 + tt] = w * (vj - vi);
            }
        } else {
            #pragma unroll
            for (int tt = 0; tt < 32; tt++) mhi[tt] = 0.0f;
        }
    }

    // ---- LN1 (width 128) in registers ----
    {
        float s_lo = 0.f, q_lo = 0.f, s_hi = 0.f, q_hi = 0.f;
        #pragma unroll
        for (int tt = 0; tt < 32; tt++) {
            s_lo += mlo[tt]; q_lo += mlo[tt] * mlo[tt];
            s_hi += mhi[tt]; q_hi += mhi[tt] * mhi[tt];
        }
        #pragma unroll
        for (int o = 1; o <= 2; o <<= 1) {
            s_lo += __shfl_xor_sync(0xffffffffu, s_lo, o);
            q_lo += __shfl_xor_sync(0xffffffffu, q_lo, o);
            s_hi += __shfl_xor_sync(0xffffffffu, s_hi, o);
            q_hi += __shfl_xor_sync(0xffffffffu, q_hi, o);
        }
        float mu_lo = s_lo * (1.0f / 128.0f);
        float mu_hi = s_hi * (1.0f / 128.0f);
        float r_l   = rsqrtf(fmaxf(q_lo * (1.0f / 128.0f) - mu_lo * mu_lo, 0.0f) + EPSF);
        float r_h   = rsqrtf(fmaxf(q_hi * (1.0f / 128.0f) - mu_hi * mu_hi, 0.0f) + EPSF);
        #pragma unroll
        for (int tt = 0; tt < 32; tt++) {
            int c = q + 4 * tt;
            float g = g1s[c], b = b1s[c];
            float h0 = (mlo[tt] - mu_lo) * r_l * g + b;
            float h1 = (mhi[tt] - mu_hi) * r_h * g + b;
            h0 = h0 > 0.f ? h0 : SLOPEF * h0;
            h1 = h1 > 0.f ? h1 : SLOPEF * h1;
            mlo[tt] = __uint_as_float(f2tf32(h0));
            mhi[tt] = __uint_as_float(f2tf32(h1));
        }
    }

    float acc[8][4];

    // ================= GEMM1 (A from registers) =================
    #pragma unroll
    for (int nt = 0; nt < 8; nt++)
        #pragma unroll
        for (int j = 0; j < 4; j++) acc[nt][j] = 0.0f;
    #pragma unroll
    for (int kt = 0; kt < 16; kt++) {
        const int k0 = kt * 8;
        uint32_t a0 = __float_as_uint(mlo[2 * kt]);
        uint32_t a1 = __float_as_uint(mhi[2 * kt]);
        uint32_t a2 = __float_as_uint(mlo[2 * kt + 1]);
        uint32_t a3 = __float_as_uint(mhi[2 * kt + 1]);
        #pragma unroll
        for (int nt = 0; nt < 8; nt++) {
            uint32_t b0 = w1u[(k0 + q) * WS + nt * 8 + grp];
            uint32_t b1 = w1u[(k0 + 4 + q) * WS + nt * 8 + grp];
            mma_tf32(acc[nt], a0, a1, a2, a3, b0, b1);
        }
    }

    // ---- LN2 in registers, write A2 (overlays w1) ----
    {
        float s_lo = 0.f, q_lo = 0.f, s_hi = 0.f, q_hi = 0.f;
        #pragma unroll
        for (int nt = 0; nt < 8; nt++) {
            s_lo += acc[nt][0] + acc[nt][1];
            q_lo += acc[nt][0]*acc[nt][0] + acc[nt][1]*acc[nt][1];
            s_hi += acc[nt][2] + acc[nt][3];
            q_hi += acc[nt][2]*acc[nt][2] + acc[nt][3]*acc[nt][3];
        }
        #pragma unroll
        for (int o = 1; o <= 2; o <<= 1) {
            s_lo += __shfl_xor_sync(0xffffffffu, s_lo, o);
            q_lo += __shfl_xor_sync(0xffffffffu, q_lo, o);
            s_hi += __shfl_xor_sync(0xffffffffu, s_hi, o);
            q_hi += __shfl_xor_sync(0xffffffffu, q_hi, o);
        }
        float mu_lo = s_lo * (1.0f/64.0f);
        float mu_hi = s_hi * (1.0f/64.0f);
        float r_l   = rsqrtf(fmaxf(q_lo * (1.0f/64.0f) - mu_lo*mu_lo, 0.0f) + EPSF);
        float r_h   = rsqrtf(fmaxf(q_hi * (1.0f/64.0f) - mu_hi*mu_hi, 0.0f) + EPSF);

        __syncthreads();   // all warps done reading w1u before A2 overlays it
        #pragma unroll
        for (int nt = 0; nt < 8; nt++) {
            int c0 = nt * 8 + 2 * q;
            float2 g = *(float2*)(g2s + c0);
            float2 b = *(float2*)(b2s + c0);
            float h0 = (acc[nt][0] - mu_lo) * r_l * g.x + b.x;
            float h1 = (acc[nt][1] - mu_lo) * r_l * g.y + b.y;
            float h2 = (acc[nt][2] - mu_hi) * r_h * g.x + b.x;
            float h3 = (acc[nt][3] - mu_hi) * r_h * g.y + b.y;
            h0 = h0 > 0.f ? h0 : SLOPEF * h0;
            h1 = h1 > 0.f ? h1 : SLOPEF * h1;
            h2 = h2 > 0.f ? h2 : SLOPEF * h2;
            h3 = h3 > 0.f ? h3 : SLOPEF * h3;
            float* o = A2 + r_lo * A2S + c0;
            *(float2*)o             = make_float2(__uint_as_float(f2tf32(h0)), __uint_as_float(f2tf32(h1)));
            *(float2*)(o + 8 * A2S) = make_float2(__uint_as_float(f2tf32(h2)), __uint_as_float(f2tf32(h3)));
        }
    }
    __syncwarp();

    // ================= GEMM2 =================
    #pragma unroll
    for (int nt = 0; nt < 8; nt++)
        #pragma unroll
        for (int j = 0; j < 4; j++) acc[nt][j] = 0.0f;
    {
        const uint32_t* Abase = (const uint32_t*)A2 + r_lo * A2S + q;
        #pragma unroll
        for (int kt = 0; kt < 8; kt++) {
            const int k0 = kt * 8;
            uint32_t a0 = Abase[k0];
            uint32_t a1 = Abase[8 * A2S + k0];
            uint32_t a2 = Abase[k0 + 4];
            uint32_t a3 = Abase[8 * A2S + k0 + 4];
            #pragma unroll
            for (int nt = 0; nt < 8; nt++) {
                uint32_t b0 = w2u[(k0 + q) * WS + nt * 8 + grp];
                uint32_t b1 = w2u[(k0 + 4 + q) * WS + nt * 8 + grp];
                mma_tf32(acc[nt], a0, a1, a2, a3, b0, b1);
            }
        }
    }

    // ---- LN3 in registers, write HB ----
    {
        float s_lo = 0.f, q_lo = 0.f, s_hi = 0.f, q_hi = 0.f;
        #pragma unroll
        for (int nt = 0; nt < 8; nt++) {
            s_lo += acc[nt][0] + acc[nt][1];
            q_lo += acc[nt][0]*acc[nt][0] + acc[nt][1]*acc[nt][1];
            s_hi += acc[nt][2] + acc[nt][3];
            q_hi += acc[nt][2]*acc[nt][2] + acc[nt][3]*acc[nt][3];
        }
        #pragma unroll
        for (int o = 1; o <= 2; o <<= 1) {
            s_lo += __shfl_xor_sync(0xffffffffu, s_lo, o);
            q_lo += __shfl_xor_sync(0xffffffffu, q_lo, o);
            s_hi += __shfl_xor_sync(0xffffffffu, s_hi, o);
            q_hi += __shfl_xor_sync(0xffffffffu, q_hi, o);
        }
        float mu_lo = s_lo * (1.0f/64.0f);
        float mu_hi = s_hi * (1.0f/64.0f);
        float r_l   = rsqrtf(fmaxf(q_lo * (1.0f/64.0f) - mu_lo*mu_lo, 0.0f) + EPSF);
        float r_h   = rsqrtf(fmaxf(q_hi * (1.0f/64.0f) - mu_hi*mu_hi, 0.0f) + EPSF);

        #pragma unroll
        for (int nt = 0; nt < 8; nt++) {
            int c0 = nt * 8 + 2 * q;
            float2 g = *(float2*)(g3s + c0);
            float2 b = *(float2*)(b3s + c0);
            float h0 = (acc[nt][0] - mu_lo) * r_l * g.x + b.x;
            float h1 = (acc[nt][1] - mu_lo) * r_l * g.y + b.y;
            float h2 = (acc[nt][2] - mu_hi) * r_h * g.x + b.x;
            float h3 = (acc[nt][3] - mu_hi) * r_h * g.y + b.y;
            h0 = h0 > 0.f ? h0 : SLOPEF * h0;
            h1 = h1 > 0.f ? h1 : SLOPEF * h1;
            h2 = h2 > 0.f ? h2 : SLOPEF * h2;
            h3 = h3 > 0.f ? h3 : SLOPEF * h3;
            float* o = HB + r_lo * A2S + c0;
            *(float2*)o             = make_float2(__uint_as_float(f2tf32(h0)), __uint_as_float(f2tf32(h1)));
            *(float2*)(o + 8 * A2S) = make_float2(__uint_as_float(f2tf32(h2)), __uint_as_float(f2tf32(h3)));
        }
    }
    __syncwarp();

    // ================= GEMM3, stage messages to smem =================
    #pragma unroll
    for (int nt = 0; nt < 8; nt++)
        #pragma unroll
        for (int j = 0; j < 4; j++) acc[nt][j] = 0.0f;
    {
        const uint32_t* Abase = (const uint32_t*)HB + r_lo * A2S + q;
        #pragma unroll
        for (int kt = 0; kt < 8; kt++) {
            const int k0 = kt * 8;
            uint32_t a0 = Abase[k0];
            uint32_t a1 = Abase[8 * A2S + k0];
            uint32_t a2 = Abase[k0 + 4];
            uint32_t a3 = Abase[8 * A2S + k0 + 4];
            #pragma unroll
            for (int nt = 0; nt < 8; nt++) {
                uint32_t b0 = w3u[(k0 + q) * WS + nt * 8 + grp];
                uint32_t b1 = w3u[(k0 + 4 + q) * WS + nt * 8 + grp];
                mma_tf32(acc[nt], a0, a1, a2, a3, b0, b1);
            }
        }
    }
    // stage raw messages (MS rows are warp-private; A2 contents dead)
    #pragma unroll
    for (int nt = 0; nt < 8; nt++) {
        int c0 = nt * 8 + 2 * q;
        float* o = MS + r_lo * A2S + c0;
        *(float2*)o             = make_float2(acc[nt][0], acc[nt][1]);
        *(float2*)(o + 8 * A2S) = make_float2(acc[nt][2], acc[nt][3]);
    }
    __syncthreads();

    // ---- run-aggregated segment-max epilogue ----
    {
        unsigned* outu = (unsigned*)out;
        const int c  = t & 63;        // output column
        const int gi = t >> 6;        // row group 0..3
        const int rs = gi * 32;
        float m = NEG_INF_F;
        int cur = tgts[rs];
        #pragma unroll 4
        for (int r = rs; r < rs + 32; r++) {
            int tg = tgts[r];
            if (tg != cur) {
                if (cur >= 0) atomicMax(outu + (unsigned)cur * HID + c, fkey(m));
                cur = tg;
                m = NEG_INF_F;
            }
            m = fmaxf(m, MS[r * A2S + c]);
        }
        if (cur >= 0) atomicMax(outu + (unsigned)cur * HID + c, fkey(m));
    }
}

extern "C" void kernel_launch(void* const* d_in, const int* in_sizes, int n_in,
                              void* d_out, int out_size) {
    const float* x  = (const float*)d_in[0];
    const float* ew = (const float*)d_in[1];
    const int*   ei = (const int*)d_in[2];
    const float* w1 = (const float*)d_in[3];
    const float* w2 = (const float*)d_in[4];
    const float* w3 = (const float*)d_in[5];
    const float* g1 = (const float*)d_in[6];
    const float* b1 = (const float*)d_in[7];
    const float* g2 = (const float*)d_in[8];
    const float* b2 = (const float*)d_in[9];
    const float* g3 = (const float*)d_in[10];
    const float* b3 = (const float*)d_in[11];
    float* out = (float*)d_out;

    const int E  = in_sizes[1];
    const int NH = out_size;
    const int N  = NH / HID;
    const int n  = N + 1;                       // scan length
    const int nchunk = (n + 1023) / 1024;

    cudaFuncSetAttribute(edge_kernel, cudaFuncAttributeMaxDynamicSharedMemorySize, SMEM_BYTES);

    // build target-sorted edge permutation
    zero_cnt_kernel<<<(n + 255) / 256, 256>>>(n);
    hist_kernel<<<(E + 255) / 256, 256>>>(ei, E);
    scan_chunk_kernel<<<nchunk, 256>>>(n);
    scan_part_kernel<<<1, 256>>>(nchunk);
    add_part_kernel<<<nchunk, 256>>>(n);
    scatter_kernel<<<(E + 255) / 256, 256>>>(ei, E);

    init_kernel<<<(NH / 4 + 255) / 256, 256>>>((uint4*)out, NH / 4);
    edge_kernel<<<(E + TILE - 1) / TILE, NTHR, SMEM_BYTES>>>(
        x, ew, ei, w1, w2, w3, g1, b1, g2, b2, g3, b3, out, E);
    finalize_kernel<<<(NH + 255) / 256, 256>>>(x, out, NH);
}